// round 2
// baseline (speedup 1.0000x reference)
#include <cuda_runtime.h>
#include <cuda_bf16.h>
#include <cstdint>

// Problem dims (fixed by the dataset)
#define B_   16
#define CIN  256
#define COUT 256
#define H_   64
#define W_   64
#define NK   4    // kernel_number n

// Scratch: combined per-batch rot matrices [B][n][9][9] and transformed
// per-batch weights wB[b][ci][co][9]  (tap-major innermost, co contiguous
// within a co-block for fast smem staging in the conv).
__device__ float g_R[B_ * NK * 81];
__device__ float g_wB[(size_t)B_ * CIN * COUT * 9];

// ---------------------------------------------------------------------------
// Kernel A: build rot matrices (one thread per (b,n)), scaled by lambda.
// ---------------------------------------------------------------------------
__global__ void rot_kernel(const float* __restrict__ thetas,
                           const float* __restrict__ scales,
                           const float* __restrict__ lambdas) {
    int id = threadIdx.x;               // 0..63 -> (b*NK + n)
    if (id >= B_ * NK) return;
    float t = thetas[id];
    float s = scales[id];
    float lam = lambdas[id];

    float x = cosf(t) * s;
    float y = sinf(t) * s;

    float m[81];
#pragma unroll
    for (int k = 0; k < 81; k++) m[k] = 0.f;
    m[4 * 9 + 4] = 1.f;  // center row

#define SET(r, c, v) m[(r) * 9 + (c)] = (v)

    bool pos = (t >= 0.f);
    bool big = (s >= 1.f);
    bool one = (fabsf(t) <= 0.78539816339744830962f);

    if (pos) {
        float a = x - y, b = x * y, c = x + y;
        float d = a * c, e = a + c;
        if (one && big) {               // pb1
            SET(0,0,a);     SET(0,1,1.f-a);
            SET(1,1,1.f-y); SET(1,2,y);
            SET(2,2,a);     SET(2,5,1.f-a);
            SET(3,0,y);     SET(3,3,1.f-y);
            SET(5,5,1.f-y); SET(5,8,y);
            SET(6,3,1.f-a); SET(6,6,a);
            SET(7,6,y);     SET(7,7,1.f-y);
            SET(8,7,1.f-a); SET(8,8,a);
        } else if (one) {               // ps1 (small, |t|<=pi/4)
            SET(0,0,d);       SET(0,1,a-d);     SET(0,3,c-d);     SET(0,4,1.f-e+d);
            SET(1,1,x-b);     SET(1,2,b);       SET(1,4,1.f-c+b); SET(1,5,y-b);
            SET(2,1,c-d);     SET(2,2,d);       SET(2,4,1.f-e+d); SET(2,5,a-d);
            SET(3,0,b);       SET(3,1,y-b);     SET(3,3,x-b);     SET(3,4,1.f-c+b);
            SET(5,4,1.f-c+b); SET(5,5,x-b);     SET(5,7,y-b);     SET(5,8,b);
            SET(6,3,a-d);     SET(6,4,1.f-e+d); SET(6,6,d);       SET(6,7,c-d);
            SET(7,3,y-b);     SET(7,4,1.f-c+b); SET(7,6,b);       SET(7,7,x-b);
            SET(8,4,1.f-e+d); SET(8,5,c-d);     SET(8,7,a-d);     SET(8,8,d);
        } else {                        // pb2 == ps2
            SET(0,0,a);       SET(0,1,1.f-a);
            SET(1,1,x-b);     SET(1,2,b);       SET(1,4,1.f-c+b); SET(1,5,y-b);
            SET(2,2,a);       SET(2,5,1.f-a);
            SET(3,0,b);       SET(3,1,y-b);     SET(3,3,x-b);     SET(3,4,1.f-c+b);
            SET(5,4,1.f-c+b); SET(5,5,x-b);     SET(5,7,y-b);     SET(5,8,b);
            SET(6,3,1.f-a);   SET(6,6,a);
            SET(7,3,y-b);     SET(7,4,1.f-c+b); SET(7,6,b);       SET(7,7,x-b);
            SET(8,7,1.f-a);   SET(8,8,a);
        }
    } else {
        float yp = -y;
        float ap = x - yp, bp = x * yp, cp = x + yp;
        float dp = ap * cp, ep = ap + cp;
        if (one && big) {               // nb1
            SET(0,0,cp);     SET(0,3,1.f-cp);
            SET(1,0,yp);     SET(1,1,1.f-yp);
            SET(2,1,1.f-cp); SET(2,2,cp);
            SET(3,3,1.f-yp); SET(3,6,yp);
            SET(5,2,yp);     SET(5,5,1.f-yp);
            SET(6,6,cp);     SET(6,7,1.f-cp);
            SET(7,7,1.f-yp); SET(7,8,yp);
            SET(8,5,1.f-cp); SET(8,8,cp);
        } else if (one) {               // ns1
            SET(0,0,dp);        SET(0,1,cp-dp);     SET(0,3,ap-dp);     SET(0,4,1.f-ep+dp);
            SET(1,0,bp);        SET(1,1,x-bp);      SET(1,3,yp-bp);     SET(1,4,1.f-cp+bp);
            SET(2,1,ap-dp);     SET(2,2,dp);        SET(2,4,1.f-ep+dp); SET(2,5,cp-dp);
            SET(3,1,yp-bp);     SET(3,2,bp);        SET(3,4,1.f-cp+bp); SET(3,5,x-bp);
            SET(5,3,x-bp);      SET(5,4,1.f-cp+bp); SET(5,6,bp);        SET(5,7,yp-bp);
            SET(6,3,cp-dp);     SET(6,4,1.f-ep+dp); SET(6,6,dp);        SET(6,7,ap-dp);
            SET(7,4,1.f-cp+bp); SET(7,5,yp-bp);     SET(7,7,x-bp);      SET(7,8,bp);
            SET(8,4,1.f-ep+dp); SET(8,5,ap-dp);     SET(8,7,cp-dp);     SET(8,8,dp);
        } else {                        // nb2 == ns2
            SET(0,0,cp);        SET(0,3,1.f-cp);
            SET(1,0,bp);        SET(1,1,x-bp);      SET(1,3,yp-bp);     SET(1,4,1.f-cp+bp);
            SET(2,1,1.f-cp);    SET(2,2,cp);
            SET(3,3,x-bp);      SET(3,4,1.f-cp+bp); SET(3,6,bp);        SET(3,7,yp-bp);
            SET(5,1,yp-bp);     SET(5,2,bp);        SET(5,4,1.f-cp+bp); SET(5,5,x-bp);
            SET(6,6,cp);        SET(6,7,1.f-cp);
            SET(7,4,1.f-cp+bp); SET(7,5,yp-bp);     SET(7,7,x-bp);      SET(7,8,bp);
            SET(8,5,1.f-cp);    SET(8,8,cp);
        }
    }
#undef SET

    float* dst = g_R + id * 81;
#pragma unroll
    for (int k = 0; k < 81; k++) dst[k] = lam * m[k];
}

// ---------------------------------------------------------------------------
// Kernel B: per-batch weight transform.
// wB[b][ci][co][i] = sum_{n,j} R[b][n][i][j] * W[n][co][ci][j]
// grid: (COUT, B), block: 256 threads over ci.
// ---------------------------------------------------------------------------
__global__ void wtrans_kernel(const float* __restrict__ weight) {
    int o = blockIdx.x;
    int b = blockIdx.y;
    int c = threadIdx.x;

    __shared__ float Rs[NK * 81];
    for (int k = threadIdx.x; k < NK * 81; k += blockDim.x)
        Rs[k] = g_R[b * NK * 81 + k];
    __syncthreads();

    float acc[9];
#pragma unroll
    for (int i = 0; i < 9; i++) acc[i] = 0.f;

#pragma unroll
    for (int n = 0; n < NK; n++) {
        float w9[9];
        const float* wp = weight + (((size_t)n * COUT + o) * CIN + c) * 9;
#pragma unroll
        for (int j = 0; j < 9; j++) w9[j] = wp[j];
#pragma unroll
        for (int i = 0; i < 9; i++) {
#pragma unroll
            for (int j = 0; j < 9; j++)
                acc[i] += Rs[n * 81 + i * 9 + j] * w9[j];
        }
    }

    float* dst = g_wB + (((size_t)b * CIN + c) * COUT + o) * 9;
#pragma unroll
    for (int i = 0; i < 9; i++) dst[i] = acc[i];
}

// ---------------------------------------------------------------------------
// Kernel C: per-sample 3x3 conv, pad=1.
// Tile: 32x32 spatial, 8 Cout per block, 2x2 pixels per thread.
// grid: (4 tiles, 32 co-blocks, 16 batch), block: 256 threads.
// ---------------------------------------------------------------------------
#define XS_STRIDE 36
__global__ void __launch_bounds__(256)
conv_kernel(const float* __restrict__ x, float* __restrict__ out) {
    __shared__ float xs[34 * XS_STRIDE];
    __shared__ float ws[8 * 9];

    int tile = blockIdx.x;           // 0..3
    int cob  = blockIdx.y;           // 0..31
    int b    = blockIdx.z;           // 0..15
    int h0 = (tile >> 1) * 32;
    int w0 = (tile & 1) * 32;
    int co0 = cob * 8;

    int tid = threadIdx.x;
    int qx = tid & 15, qy = tid >> 4;
    int ph = qy * 2, pw = qx * 2;    // pixel base within tile

    float acc[8][2][2];
#pragma unroll
    for (int co = 0; co < 8; co++)
#pragma unroll
        for (int py = 0; py < 2; py++)
#pragma unroll
            for (int px = 0; px < 2; px++) acc[co][py][px] = 0.f;

    const float* xb = x + (size_t)b * CIN * (H_ * W_);
    const float* wb = g_wB + (size_t)b * CIN * COUT * 9 + (size_t)co0 * 9;

    for (int ci = 0; ci < CIN; ci++) {
        const float* xc = xb + (size_t)ci * (H_ * W_);
        // stage x tile with halo (34x34) into smem, zero-padded
        for (int idx = tid; idx < 34 * 34; idx += 256) {
            int r = idx / 34;
            int cc = idx - r * 34;
            int gh = h0 - 1 + r;
            int gw = w0 - 1 + cc;
            float v = 0.f;
            if (gh >= 0 && gh < H_ && gw >= 0 && gw < W_) v = xc[gh * W_ + gw];
            xs[r * XS_STRIDE + cc] = v;
        }
        // stage weights for 8 Cout x 9 taps (contiguous 72 floats)
        if (tid < 72) ws[tid] = wb[(size_t)ci * COUT * 9 + tid];
        __syncthreads();

        // 4x4 input neighborhood for the 2x2 pixel quad
        float xv[4][4];
#pragma unroll
        for (int r = 0; r < 4; r++) {
            float2 p0 = *(const float2*)&xs[(ph + r) * XS_STRIDE + pw];
            float2 p1 = *(const float2*)&xs[(ph + r) * XS_STRIDE + pw + 2];
            xv[r][0] = p0.x; xv[r][1] = p0.y; xv[r][2] = p1.x; xv[r][3] = p1.y;
        }

#pragma unroll
        for (int co = 0; co < 8; co++) {
#pragma unroll
            for (int dh = 0; dh < 3; dh++) {
#pragma unroll
                for (int dw = 0; dw < 3; dw++) {
                    float w = ws[co * 9 + dh * 3 + dw];
                    acc[co][0][0] += w * xv[dh    ][dw    ];
                    acc[co][0][1] += w * xv[dh    ][dw + 1];
                    acc[co][1][0] += w * xv[dh + 1][dw    ];
                    acc[co][1][1] += w * xv[dh + 1][dw + 1];
                }
            }
        }
        __syncthreads();
    }

    // write output as float2 (coalesced pairs)
#pragma unroll
    for (int co = 0; co < 8; co++) {
#pragma unroll
        for (int py = 0; py < 2; py++) {
            size_t o_off = (((size_t)b * COUT + co0 + co) * H_ + (h0 + ph + py)) * W_
                           + (w0 + pw);
            *(float2*)&out[o_off] = make_float2(acc[co][py][0], acc[co][py][1]);
        }
    }
}

// ---------------------------------------------------------------------------
extern "C" void kernel_launch(void* const* d_in, const int* in_sizes, int n_in,
                              void* d_out, int out_size) {
    const float* x       = (const float*)d_in[0];
    const float* thetas  = (const float*)d_in[1];
    const float* scales  = (const float*)d_in[2];
    const float* lambdas = (const float*)d_in[3];
    const float* weight  = (const float*)d_in[4];
    float* out = (float*)d_out;

    rot_kernel<<<1, 64>>>(thetas, scales, lambdas);
    wtrans_kernel<<<dim3(COUT, B_), 256>>>(weight);
    conv_kernel<<<dim3(4, 32, B_), 256>>>(x, out);
}

// round 3
// speedup vs baseline: 1.1704x; 1.1704x over previous
#include <cuda_runtime.h>
#include <cuda_bf16.h>
#include <cstdint>

// Problem dims (fixed by the dataset)
#define B_   16
#define CIN  256
#define COUT 256
#define H_   64
#define W_   64
#define NK   4    // kernel_number n

typedef unsigned long long u64;

// Scratch: per-batch rot matrices [B][n][9][9] and transformed per-batch
// weights wB[b][ci][co][9] (co contiguous within a block of 8 for staging).
__device__ float g_R[B_ * NK * 81];
__device__ float g_wB[(size_t)B_ * CIN * COUT * 9];

// ---------------------------------------------------------------------------
// f32x2 packed-math helpers (sm_100+ PTX; SASS FFMA2 — 2 fp32 FMAs / instr)
// ---------------------------------------------------------------------------
__device__ __forceinline__ u64 pack2(float lo, float hi) {
    u64 r; asm("mov.b64 %0, {%1, %2};" : "=l"(r) : "f"(lo), "f"(hi)); return r;
}
__device__ __forceinline__ u64 fma2(u64 a, u64 b, u64 c) {
    u64 d; asm("fma.rn.f32x2 %0, %1, %2, %3;" : "=l"(d) : "l"(a), "l"(b), "l"(c)); return d;
}
__device__ __forceinline__ float2 unpack2(u64 v) {
    float2 f; asm("mov.b64 {%0, %1}, %2;" : "=f"(f.x), "=f"(f.y) : "l"(v)); return f;
}

// ---------------------------------------------------------------------------
// Kernel A: build rot matrices (one thread per (b,n)), scaled by lambda.
// ---------------------------------------------------------------------------
__global__ void rot_kernel(const float* __restrict__ thetas,
                           const float* __restrict__ scales,
                           const float* __restrict__ lambdas) {
    int id = threadIdx.x;               // 0..63 -> (b*NK + n)
    if (id >= B_ * NK) return;
    float t = thetas[id];
    float s = scales[id];
    float lam = lambdas[id];

    float x = cosf(t) * s;
    float y = sinf(t) * s;

    float m[81];
#pragma unroll
    for (int k = 0; k < 81; k++) m[k] = 0.f;
    m[4 * 9 + 4] = 1.f;  // center row

#define SET(r, c, v) m[(r) * 9 + (c)] = (v)

    bool pos = (t >= 0.f);
    bool big = (s >= 1.f);
    bool one = (fabsf(t) <= 0.78539816339744830962f);

    if (pos) {
        float a = x - y, b = x * y, c = x + y;
        float d = a * c, e = a + c;
        if (one && big) {               // pb1
            SET(0,0,a);     SET(0,1,1.f-a);
            SET(1,1,1.f-y); SET(1,2,y);
            SET(2,2,a);     SET(2,5,1.f-a);
            SET(3,0,y);     SET(3,3,1.f-y);
            SET(5,5,1.f-y); SET(5,8,y);
            SET(6,3,1.f-a); SET(6,6,a);
            SET(7,6,y);     SET(7,7,1.f-y);
            SET(8,7,1.f-a); SET(8,8,a);
        } else if (one) {               // ps1 (small, |t|<=pi/4)
            SET(0,0,d);       SET(0,1,a-d);     SET(0,3,c-d);     SET(0,4,1.f-e+d);
            SET(1,1,x-b);     SET(1,2,b);       SET(1,4,1.f-c+b); SET(1,5,y-b);
            SET(2,1,c-d);     SET(2,2,d);       SET(2,4,1.f-e+d); SET(2,5,a-d);
            SET(3,0,b);       SET(3,1,y-b);     SET(3,3,x-b);     SET(3,4,1.f-c+b);
            SET(5,4,1.f-c+b); SET(5,5,x-b);     SET(5,7,y-b);     SET(5,8,b);
            SET(6,3,a-d);     SET(6,4,1.f-e+d); SET(6,6,d);       SET(6,7,c-d);
            SET(7,3,y-b);     SET(7,4,1.f-c+b); SET(7,6,b);       SET(7,7,x-b);
            SET(8,4,1.f-e+d); SET(8,5,c-d);     SET(8,7,a-d);     SET(8,8,d);
        } else {                        // pb2 == ps2
            SET(0,0,a);       SET(0,1,1.f-a);
            SET(1,1,x-b);     SET(1,2,b);       SET(1,4,1.f-c+b); SET(1,5,y-b);
            SET(2,2,a);       SET(2,5,1.f-a);
            SET(3,0,b);       SET(3,1,y-b);     SET(3,3,x-b);     SET(3,4,1.f-c+b);
            SET(5,4,1.f-c+b); SET(5,5,x-b);     SET(5,7,y-b);     SET(5,8,b);
            SET(6,3,1.f-a);   SET(6,6,a);
            SET(7,3,y-b);     SET(7,4,1.f-c+b); SET(7,6,b);       SET(7,7,x-b);
            SET(8,7,1.f-a);   SET(8,8,a);
        }
    } else {
        float yp = -y;
        float ap = x - yp, bp = x * yp, cp = x + yp;
        float dp = ap * cp, ep = ap + cp;
        if (one && big) {               // nb1
            SET(0,0,cp);     SET(0,3,1.f-cp);
            SET(1,0,yp);     SET(1,1,1.f-yp);
            SET(2,1,1.f-cp); SET(2,2,cp);
            SET(3,3,1.f-yp); SET(3,6,yp);
            SET(5,2,yp);     SET(5,5,1.f-yp);
            SET(6,6,cp);     SET(6,7,1.f-cp);
            SET(7,7,1.f-yp); SET(7,8,yp);
            SET(8,5,1.f-cp); SET(8,8,cp);
        } else if (one) {               // ns1
            SET(0,0,dp);        SET(0,1,cp-dp);     SET(0,3,ap-dp);     SET(0,4,1.f-ep+dp);
            SET(1,0,bp);        SET(1,1,x-bp);      SET(1,3,yp-bp);     SET(1,4,1.f-cp+bp);
            SET(2,1,ap-dp);     SET(2,2,dp);        SET(2,4,1.f-ep+dp); SET(2,5,cp-dp);
            SET(3,1,yp-bp);     SET(3,2,bp);        SET(3,4,1.f-cp+bp); SET(3,5,x-bp);
            SET(5,3,x-bp);      SET(5,4,1.f-cp+bp); SET(5,6,bp);        SET(5,7,yp-bp);
            SET(6,3,cp-dp);     SET(6,4,1.f-ep+dp); SET(6,6,dp);        SET(6,7,ap-dp);
            SET(7,4,1.f-cp+bp); SET(7,5,yp-bp);     SET(7,7,x-bp);      SET(7,8,bp);
            SET(8,4,1.f-ep+dp); SET(8,5,ap-dp);     SET(8,7,cp-dp);     SET(8,8,dp);
        } else {                        // nb2 == ns2
            SET(0,0,cp);        SET(0,3,1.f-cp);
            SET(1,0,bp);        SET(1,1,x-bp);      SET(1,3,yp-bp);     SET(1,4,1.f-cp+bp);
            SET(2,1,1.f-cp);    SET(2,2,cp);
            SET(3,3,x-bp);      SET(3,4,1.f-cp+bp); SET(3,6,bp);        SET(3,7,yp-bp);
            SET(5,1,yp-bp);     SET(5,2,bp);        SET(5,4,1.f-cp+bp); SET(5,5,x-bp);
            SET(6,6,cp);        SET(6,7,1.f-cp);
            SET(7,4,1.f-cp+bp); SET(7,5,yp-bp);     SET(7,7,x-bp);      SET(7,8,bp);
            SET(8,5,1.f-cp);    SET(8,8,cp);
        }
    }
#undef SET

    float* dst = g_R + id * 81;
#pragma unroll
    for (int k = 0; k < 81; k++) dst[k] = lam * m[k];
}

// ---------------------------------------------------------------------------
// Kernel B: per-batch weight transform.
// wB[b][ci][co][i] = sum_{n,j} R[b][n][i][j] * W[n][co][ci][j]
// grid: (COUT, B), block: 256 threads over ci.
// ---------------------------------------------------------------------------
__global__ void wtrans_kernel(const float* __restrict__ weight) {
    int o = blockIdx.x;
    int b = blockIdx.y;
    int c = threadIdx.x;

    __shared__ float Rs[NK * 81];
    for (int k = threadIdx.x; k < NK * 81; k += blockDim.x)
        Rs[k] = g_R[b * NK * 81 + k];
    __syncthreads();

    float acc[9];
#pragma unroll
    for (int i = 0; i < 9; i++) acc[i] = 0.f;

#pragma unroll
    for (int n = 0; n < NK; n++) {
        float w9[9];
        const float* wp = weight + (((size_t)n * COUT + o) * CIN + c) * 9;
#pragma unroll
        for (int j = 0; j < 9; j++) w9[j] = wp[j];
#pragma unroll
        for (int i = 0; i < 9; i++) {
#pragma unroll
            for (int j = 0; j < 9; j++)
                acc[i] += Rs[n * 81 + i * 9 + j] * w9[j];
        }
    }

    float* dst = g_wB + (((size_t)b * CIN + c) * COUT + o) * 9;
#pragma unroll
    for (int i = 0; i < 9; i++) dst[i] = acc[i];
}

// ---------------------------------------------------------------------------
// Kernel C: per-sample 3x3 conv with packed f32x2 FMA.
// Tile: 16 rows x 64 cols, 8 Cout per block. 256 threads: each thread
// computes 1 row x 4 cols (two f32x2 pairs) x 8 Cout.
// 4 input channels staged per barrier phase.
// grid: (4 h-tiles, 32 co-blocks, 16 batch)
// ---------------------------------------------------------------------------
#define XSTR   66        // xs row stride (floats), even -> 8B-aligned pairs
#define TROWS  16        // output rows per block
#define HROWS  18        // staged rows incl. halo
#define CI_STG 4         // channels per staging phase

__global__ void __launch_bounds__(256, 2)
conv_kernel(const float* __restrict__ x, float* __restrict__ out) {
    __shared__ float xs[CI_STG * HROWS * XSTR];
    __shared__ u64 ws2[CI_STG * 72];          // (w,w) duplicated pairs

    int ht  = blockIdx.x;            // 0..3
    int cob = blockIdx.y;            // 0..31
    int b   = blockIdx.z;            // 0..15
    int h0  = ht * TROWS;
    int co0 = cob * 8;

    int tid = threadIdx.x;
    int qx = tid & 15;               // col group: cols 4qx..4qx+3
    int r  = tid >> 4;               // output row within tile (0..15)

    u64 accA[8], accB[8];            // pairs (c, c+1) and (c+2, c+3)
#pragma unroll
    for (int co = 0; co < 8; co++) { accA[co] = 0ull; accB[co] = 0ull; }

    const float* xb = x + (size_t)b * CIN * (H_ * W_);
    const float* wbase = g_wB + ((size_t)b * CIN * COUT + co0) * 9;

    for (int cig = 0; cig < CIN; cig += CI_STG) {
        __syncthreads();   // previous compute done before smem overwrite
        // ---- stage 4 channels of x (with halo, zero-padded) ----
        for (int idx = tid; idx < CI_STG * HROWS * 66; idx += 256) {
            int ch  = idx / (HROWS * 66);
            int rem = idx - ch * (HROWS * 66);
            int rr  = rem / 66;
            int cc  = rem - rr * 66;
            int gh = h0 - 1 + rr;
            int gw = cc - 1;
            float v = 0.f;
            if (gh >= 0 && gh < H_ && (unsigned)gw < (unsigned)W_)
                v = xb[(size_t)(cig + ch) * (H_ * W_) + gh * W_ + gw];
            xs[ch * (HROWS * XSTR) + rr * XSTR + cc] = v;
        }
        // ---- stage 4 channels of weights, duplicated into pairs ----
        for (int idx = tid; idx < CI_STG * 72; idx += 256) {
            int ch = idx / 72;
            int k  = idx - ch * 72;
            float w = wbase[(size_t)(cig + ch) * COUT * 9 + k];
            ws2[idx] = pack2(w, w);
        }
        __syncthreads();

#pragma unroll
        for (int s = 0; s < CI_STG; s++) {
            // input window: xs rows r..r+2 (xs row 0 == global h0-1),
            // xs cols 4qx..4qx+5 == global cols 4qx-1..4qx+4
            const float* xsc = xs + s * (HROWS * XSTR) + r * XSTR + 4 * qx;
            u64 S0[3], S1[3], S2[3], P1[3], P2[3];
#pragma unroll
            for (int ir = 0; ir < 3; ir++) {
                float2 a0 = *(const float2*)(xsc + ir * XSTR);      // (v-1, v0)
                float2 a1 = *(const float2*)(xsc + ir * XSTR + 2);  // (v1, v2)
                float2 a2 = *(const float2*)(xsc + ir * XSTR + 4);  // (v3, v4)
                S0[ir] = pack2(a0.x, a0.y);
                S1[ir] = pack2(a1.x, a1.y);
                S2[ir] = pack2(a2.x, a2.y);
                P1[ir] = pack2(a0.y, a1.x);                          // (v0, v1)
                P2[ir] = pack2(a1.y, a2.x);                          // (v2, v3)
            }
            const u64* wp = ws2 + s * 72;
#pragma unroll
            for (int co = 0; co < 8; co++) {
#pragma unroll
                for (int ir = 0; ir < 3; ir++) {
                    u64 w0 = wp[co * 9 + ir * 3 + 0];
                    u64 w1 = wp[co * 9 + ir * 3 + 1];
                    u64 w2 = wp[co * 9 + ir * 3 + 2];
                    // pairA = out cols (4qx, 4qx+1); pairB = (4qx+2, 4qx+3)
                    accA[co] = fma2(w0, S0[ir], accA[co]);
                    accB[co] = fma2(w0, S1[ir], accB[co]);
                    accA[co] = fma2(w1, P1[ir], accA[co]);
                    accB[co] = fma2(w1, P2[ir], accB[co]);
                    accA[co] = fma2(w2, S1[ir], accA[co]);
                    accB[co] = fma2(w2, S2[ir], accB[co]);
                }
            }
        }
    }

    // ---- store: one float4 per (thread, co) ----
    int h = h0 + r;
#pragma unroll
    for (int co = 0; co < 8; co++) {
        float2 a = unpack2(accA[co]);
        float2 c2 = unpack2(accB[co]);
        float4 v = make_float4(a.x, a.y, c2.x, c2.y);
        size_t off = (((size_t)b * COUT + co0 + co) * H_ + h) * W_ + 4 * qx;
        *(float4*)&out[off] = v;
    }
}

// ---------------------------------------------------------------------------
extern "C" void kernel_launch(void* const* d_in, const int* in_sizes, int n_in,
                              void* d_out, int out_size) {
    const float* x       = (const float*)d_in[0];
    const float* thetas  = (const float*)d_in[1];
    const float* scales  = (const float*)d_in[2];
    const float* lambdas = (const float*)d_in[3];
    const float* weight  = (const float*)d_in[4];
    float* out = (float*)d_out;

    rot_kernel<<<1, 64>>>(thetas, scales, lambdas);
    wtrans_kernel<<<dim3(COUT, B_), 256>>>(weight);
    conv_kernel<<<dim3(4, 32, B_), 256>>>(x, out);
}

// round 6
// speedup vs baseline: 4.2752x; 3.6528x over previous
#include <cuda_runtime.h>
#include <cuda_bf16.h>
#include <cstdint>

// Problem dims (fixed by the dataset)
#define B_   16
#define CIN  256
#define COUT 256
#define H_   64
#define W_   64
#define NK   4    // kernel_number n

// Padded-pixel geometry: 66x66 grid flattened; tap shift = (dh-1)*66+(dw-1)
#define POFF   68          // row margin so shifted reads never go negative
#define PROWS  4616
#define NTILE  128         // pixels (M) per CTA
#define NTILES 35          // ceil(4356/128)

typedef unsigned long long u64;

// -------------------- device scratch (static, no allocs) --------------------
__device__ float g_R[B_ * NK * 81];
__device__ __align__(256) __nv_bfloat16 g_xhi[(size_t)B_ * PROWS * CIN];
__device__ __align__(256) __nv_bfloat16 g_xlo[(size_t)B_ * PROWS * CIN];
__device__ __align__(256) __nv_bfloat16 g_whi[(size_t)B_ * 9 * COUT * CIN];
__device__ __align__(256) __nv_bfloat16 g_wlo[(size_t)B_ * 9 * COUT * CIN];

// -------------------- PTX helpers (plain sm_90-safe, no 'a' features) ------
__device__ __forceinline__ uint32_t smem_u32(const void* p) {
    uint32_t a;
    asm("{ .reg .u64 t; cvta.to.shared.u64 t, %1; cvt.u32.u64 %0, t; }"
        : "=r"(a) : "l"(p));
    return a;
}

#define CP16(dst, src) \
    asm volatile("cp.async.cg.shared.global [%0], [%1], 16;" \
                 :: "r"(dst), "l"(src) : "memory")
#define CP_COMMIT() asm volatile("cp.async.commit_group;" ::: "memory")
#define CP_WAIT1()  asm volatile("cp.async.wait_group 1;" ::: "memory")
#define CP_WAIT0()  asm volatile("cp.async.wait_group 0;" ::: "memory")

__device__ __forceinline__ void ldm4(uint32_t& r0, uint32_t& r1,
                                     uint32_t& r2, uint32_t& r3, uint32_t a) {
    asm volatile("ldmatrix.sync.aligned.m8n8.x4.shared.b16 {%0,%1,%2,%3}, [%4];"
                 : "=r"(r0), "=r"(r1), "=r"(r2), "=r"(r3) : "r"(a));
}

__device__ __forceinline__ void mma16816(float* c, const uint32_t* a,
                                         const uint32_t* b) {
    asm volatile(
        "mma.sync.aligned.m16n8k16.row.col.f32.bf16.bf16.f32 "
        "{%0,%1,%2,%3}, {%4,%5,%6,%7}, {%8,%9}, {%0,%1,%2,%3};"
        : "+f"(c[0]), "+f"(c[1]), "+f"(c[2]), "+f"(c[3])
        : "r"(a[0]), "r"(a[1]), "r"(a[2]), "r"(a[3]), "r"(b[0]), "r"(b[1]));
}

// ---------------------------------------------------------------------------
// Kernel A: rot matrices (one thread per (b,n)), scaled by lambda.
// ---------------------------------------------------------------------------
__global__ void rot_kernel(const float* __restrict__ thetas,
                           const float* __restrict__ scales,
                           const float* __restrict__ lambdas) {
    int id = threadIdx.x;
    if (id >= B_ * NK) return;
    float t = thetas[id];
    float s = scales[id];
    float lam = lambdas[id];

    float x = cosf(t) * s;
    float y = sinf(t) * s;

    float m[81];
#pragma unroll
    for (int k = 0; k < 81; k++) m[k] = 0.f;
    m[4 * 9 + 4] = 1.f;

#define SET(r, c, v) m[(r) * 9 + (c)] = (v)
    bool pos = (t >= 0.f);
    bool big = (s >= 1.f);
    bool one = (fabsf(t) <= 0.78539816339744830962f);

    if (pos) {
        float a = x - y, b = x * y, c = x + y;
        float d = a * c, e = a + c;
        if (one && big) {
            SET(0,0,a);     SET(0,1,1.f-a);
            SET(1,1,1.f-y); SET(1,2,y);
            SET(2,2,a);     SET(2,5,1.f-a);
            SET(3,0,y);     SET(3,3,1.f-y);
            SET(5,5,1.f-y); SET(5,8,y);
            SET(6,3,1.f-a); SET(6,6,a);
            SET(7,6,y);     SET(7,7,1.f-y);
            SET(8,7,1.f-a); SET(8,8,a);
        } else if (one) {
            SET(0,0,d);       SET(0,1,a-d);     SET(0,3,c-d);     SET(0,4,1.f-e+d);
            SET(1,1,x-b);     SET(1,2,b);       SET(1,4,1.f-c+b); SET(1,5,y-b);
            SET(2,1,c-d);     SET(2,2,d);       SET(2,4,1.f-e+d); SET(2,5,a-d);
            SET(3,0,b);       SET(3,1,y-b);     SET(3,3,x-b);     SET(3,4,1.f-c+b);
            SET(5,4,1.f-c+b); SET(5,5,x-b);     SET(5,7,y-b);     SET(5,8,b);
            SET(6,3,a-d);     SET(6,4,1.f-e+d); SET(6,6,d);       SET(6,7,c-d);
            SET(7,3,y-b);     SET(7,4,1.f-c+b); SET(7,6,b);       SET(7,7,x-b);
            SET(8,4,1.f-e+d); SET(8,5,c-d);     SET(8,7,a-d);     SET(8,8,d);
        } else {
            SET(0,0,a);       SET(0,1,1.f-a);
            SET(1,1,x-b);     SET(1,2,b);       SET(1,4,1.f-c+b); SET(1,5,y-b);
            SET(2,2,a);       SET(2,5,1.f-a);
            SET(3,0,b);       SET(3,1,y-b);     SET(3,3,x-b);     SET(3,4,1.f-c+b);
            SET(5,4,1.f-c+b); SET(5,5,x-b);     SET(5,7,y-b);     SET(5,8,b);
            SET(6,3,1.f-a);   SET(6,6,a);
            SET(7,3,y-b);     SET(7,4,1.f-c+b); SET(7,6,b);       SET(7,7,x-b);
            SET(8,7,1.f-a);   SET(8,8,a);
        }
    } else {
        float yp = -y;
        float ap = x - yp, bp = x * yp, cp = x + yp;
        float dp = ap * cp, ep = ap + cp;
        if (one && big) {
            SET(0,0,cp);     SET(0,3,1.f-cp);
            SET(1,0,yp);     SET(1,1,1.f-yp);
            SET(2,1,1.f-cp); SET(2,2,cp);
            SET(3,3,1.f-yp); SET(3,6,yp);
            SET(5,2,yp);     SET(5,5,1.f-yp);
            SET(6,6,cp);     SET(6,7,1.f-cp);
            SET(7,7,1.f-yp); SET(7,8,yp);
            SET(8,5,1.f-cp); SET(8,8,cp);
        } else if (one) {
            SET(0,0,dp);        SET(0,1,cp-dp);     SET(0,3,ap-dp);     SET(0,4,1.f-ep+dp);
            SET(1,0,bp);        SET(1,1,x-bp);      SET(1,3,yp-bp);     SET(1,4,1.f-cp+bp);
            SET(2,1,ap-dp);     SET(2,2,dp);        SET(2,4,1.f-ep+dp); SET(2,5,cp-dp);
            SET(3,1,yp-bp);     SET(3,2,bp);        SET(3,4,1.f-cp+bp); SET(3,5,x-bp);
            SET(5,3,x-bp);      SET(5,4,1.f-cp+bp); SET(5,6,bp);        SET(5,7,yp-bp);
            SET(6,3,cp-dp);     SET(6,4,1.f-ep+dp); SET(6,6,dp);        SET(6,7,ap-dp);
            SET(7,4,1.f-cp+bp); SET(7,5,yp-bp);     SET(7,7,x-bp);      SET(7,8,bp);
            SET(8,4,1.f-ep+dp); SET(8,5,ap-dp);     SET(8,7,cp-dp);     SET(8,8,dp);
        } else {
            SET(0,0,cp);        SET(0,3,1.f-cp);
            SET(1,0,bp);        SET(1,1,x-bp);      SET(1,3,yp-bp);     SET(1,4,1.f-cp+bp);
            SET(2,1,1.f-cp);    SET(2,2,cp);
            SET(3,3,x-bp);      SET(3,4,1.f-cp+bp); SET(3,6,bp);        SET(3,7,yp-bp);
            SET(5,1,yp-bp);     SET(5,2,bp);        SET(5,4,1.f-cp+bp); SET(5,5,x-bp);
            SET(6,6,cp);        SET(6,7,1.f-cp);
            SET(7,4,1.f-cp+bp); SET(7,5,yp-bp);     SET(7,7,x-bp);      SET(7,8,bp);
            SET(8,5,1.f-cp);    SET(8,8,cp);
        }
    }
#undef SET

    float* dst = g_R + id * 81;
#pragma unroll
    for (int k = 0; k < 81; k++) dst[k] = lam * m[k];
}

// ---------------------------------------------------------------------------
// Kernel B: weight transform + bf16 hi/lo split.
// g_w{hi,lo}[b][tap][co][ci] = split( sum_{n,j} R[b][n][tap][j] * W[n][co][ci][j] )
// ---------------------------------------------------------------------------
__global__ void wtrans_kernel(const float* __restrict__ weight) {
    int o = blockIdx.x;     // co
    int b = blockIdx.y;
    int c = threadIdx.x;    // ci

    __shared__ float Rs[NK * 81];
    for (int k = threadIdx.x; k < NK * 81; k += blockDim.x)
        Rs[k] = g_R[b * NK * 81 + k];
    __syncthreads();

    float acc[9];
#pragma unroll
    for (int i = 0; i < 9; i++) acc[i] = 0.f;

#pragma unroll
    for (int n = 0; n < NK; n++) {
        float w9[9];
        const float* wp = weight + (((size_t)n * COUT + o) * CIN + c) * 9;
#pragma unroll
        for (int j = 0; j < 9; j++) w9[j] = wp[j];
#pragma unroll
        for (int i = 0; i < 9; i++)
#pragma unroll
            for (int j = 0; j < 9; j++)
                acc[i] += Rs[n * 81 + i * 9 + j] * w9[j];
    }

#pragma unroll
    for (int i = 0; i < 9; i++) {
        __nv_bfloat16 hi = __float2bfloat16(acc[i]);
        __nv_bfloat16 lo = __float2bfloat16(acc[i] - __bfloat162float(hi));
        size_t idx = (((size_t)b * 9 + i) * COUT + o) * CIN + c;
        g_whi[idx] = hi;
        g_wlo[idx] = lo;
    }
}

// ---------------------------------------------------------------------------
// Kernel Z: zero the padded transposed-x buffers (margins + zero padding).
// ---------------------------------------------------------------------------
__global__ void xzero_kernel() {
    size_t n16 = ((size_t)B_ * PROWS * CIN * 2) / 16;
    uint4 z = make_uint4(0, 0, 0, 0);
    uint4* a = (uint4*)g_xhi;
    uint4* b = (uint4*)g_xlo;
    for (size_t i = blockIdx.x * blockDim.x + threadIdx.x; i < n16;
         i += (size_t)gridDim.x * blockDim.x) {
        a[i] = z;
        b[i] = z;
    }
}

// ---------------------------------------------------------------------------
// Kernel X: transpose + pad + bf16 split of x into g_x{hi,lo}[b][pixel][ci].
// ---------------------------------------------------------------------------
__global__ void xprep_kernel(const float* __restrict__ x) {
    __shared__ float t[64][65];
    int h = blockIdx.x, b = blockIdx.y;

    for (int ci0 = 0; ci0 < CIN; ci0 += 64) {
        __syncthreads();
        for (int i = threadIdx.x; i < 64 * 64; i += 256) {
            int cl = i >> 6, w = i & 63;
            t[cl][w] = x[(((size_t)b * CIN + ci0 + cl) * H_ + h) * W_ + w];
        }
        __syncthreads();
        for (int i = threadIdx.x; i < 64 * 64; i += 256) {
            int w = i >> 6, cl = i & 63;
            float v = t[cl][w];
            __nv_bfloat16 hi = __float2bfloat16(v);
            __nv_bfloat16 lo = __float2bfloat16(v - __bfloat162float(hi));
            size_t row = (size_t)b * PROWS + ((h + 1) * 66 + (w + 1) + POFF);
            g_xhi[row * CIN + ci0 + cl] = hi;
            g_xlo[row * CIN + ci0 + cl] = lo;
        }
    }
}

// ---------------------------------------------------------------------------
// Kernel C: implicit-GEMM conv via mma.sync (bf16, fp32 accum).
// CTA: 128 pixels x 128 cout, 8 warps (2M x 4N), warp tile 64x32.
// 36 stages (9 taps x 4 ci-chunks of 64), cp.async double-buffered.
// ---------------------------------------------------------------------------
#define LDT     144u                 // smem row stride bytes (9 x 16B)
#define TILE_B  (128u * LDT)         // 18432 B per sub-tile
#define OFF_AH  0u
#define OFF_AL  TILE_B
#define OFF_BH  (2u * TILE_B)
#define OFF_BL  (3u * TILE_B)
#define STG_B   (4u * TILE_B)        // 73728 B per stage
#define SMEM_BYTES (2u * STG_B)      // 147456 B

__device__ __forceinline__ void stage_tiles(uint32_t sdst,
                                            const char* Xh, const char* Xl,
                                            const char* Wh, const char* Wl,
                                            int c0, int co0, int st, int tid) {
    const int tap = st >> 2, kc = st & 3;
    const int dlt = (tap / 3 - 1) * 66 + (tap % 3) - 1;
    const char* sAh = Xh + ((size_t)(c0 + dlt + POFF) * CIN + kc * 64) * 2;
    const char* sAl = Xl + ((size_t)(c0 + dlt + POFF) * CIN + kc * 64) * 2;
    const char* sBh = Wh + (((size_t)tap * COUT + co0) * CIN + kc * 64) * 2;
    const char* sBl = Wl + (((size_t)tap * COUT + co0) * CIN + kc * 64) * 2;
#pragma unroll
    for (int j = 0; j < 4; j++) {
        int idx = j * 256 + tid;              // 0..1023
        int row = idx >> 3, seg = idx & 7;
        uint32_t d = sdst + row * LDT + seg * 16;
        size_t  so = (size_t)row * (CIN * 2) + seg * 16;
        CP16(d + OFF_AH, sAh + so);
        CP16(d + OFF_AL, sAl + so);
        CP16(d + OFF_BH, sBh + so);
        CP16(d + OFF_BL, sBl + so);
    }
}

__global__ void __launch_bounds__(256, 1)
conv_mma_kernel(float* __restrict__ out) {
    extern __shared__ char smem[];
    const uint32_t sb = smem_u32(smem);

    const int tid = threadIdx.x;
    const int wid = tid >> 5, lane = tid & 31;
    const int wm = wid >> 2;         // 0..1 : M half (64 rows)
    const int wn = wid & 3;          // 0..3 : N quarter (32 cols)
    const int tile = blockIdx.x, cob = blockIdx.y, b = blockIdx.z;
    const int c0 = tile * NTILE;
    const int co0 = cob * 128;

    const char* Xh = (const char*)(g_xhi + (size_t)b * PROWS * CIN);
    const char* Xl = (const char*)(g_xlo + (size_t)b * PROWS * CIN);
    const char* Wh = (const char*)(g_whi + (size_t)b * 9 * COUT * CIN);
    const char* Wl = (const char*)(g_wlo + (size_t)b * 9 * COUT * CIN);

    float acc[4][4][4];
#pragma unroll
    for (int mt = 0; mt < 4; mt++)
#pragma unroll
        for (int nt = 0; nt < 4; nt++)
#pragma unroll
            for (int k = 0; k < 4; k++) acc[mt][nt][k] = 0.f;

    // per-lane ldmatrix address components
    const uint32_t aRow = (uint32_t)(wm * 64 + (lane & 15)) * LDT + (lane >> 4) * 16;
    const uint32_t bRow = (uint32_t)(wn * 32 + ((lane >> 4) * 8 + (lane & 7))) * LDT
                          + ((lane >> 3) & 1) * 16;

    stage_tiles(sb, Xh, Xl, Wh, Wl, c0, co0, 0, tid);
    CP_COMMIT();

    for (int st = 0; st < 36; st++) {
        if (st + 1 < 36) {
            stage_tiles(sb + ((st + 1) & 1) * STG_B, Xh, Xl, Wh, Wl,
                        c0, co0, st + 1, tid);
            CP_COMMIT();
            CP_WAIT1();
        } else {
            CP_WAIT0();
        }
        __syncthreads();

        const uint32_t buf = sb + (st & 1) * STG_B;
#pragma unroll
        for (int ks = 0; ks < 4; ks++) {
            const uint32_t kb = ks * 32;
            uint32_t bh[4][2], bl[4][2], a[4][4];
            ldm4(bh[0][0], bh[0][1], bh[1][0], bh[1][1], buf + OFF_BH + bRow + kb);
            ldm4(bh[2][0], bh[2][1], bh[3][0], bh[3][1], buf + OFF_BH + bRow + 16 * LDT + kb);
            ldm4(bl[0][0], bl[0][1], bl[1][0], bl[1][1], buf + OFF_BL + bRow + kb);
            ldm4(bl[2][0], bl[2][1], bl[3][0], bl[3][1], buf + OFF_BL + bRow + 16 * LDT + kb);
#pragma unroll
            for (int mt = 0; mt < 4; mt++)
                ldm4(a[mt][0], a[mt][1], a[mt][2], a[mt][3],
                     buf + OFF_AH + aRow + mt * (16 * LDT) + kb);
#pragma unroll
            for (int mt = 0; mt < 4; mt++)
#pragma unroll
                for (int nt = 0; nt < 4; nt++)
                    mma16816(acc[mt][nt], a[mt], bh[nt]);
#pragma unroll
            for (int mt = 0; mt < 4; mt++)
#pragma unroll
                for (int nt = 0; nt < 4; nt++)
                    mma16816(acc[mt][nt], a[mt], bl[nt]);
#pragma unroll
            for (int mt = 0; mt < 4; mt++)
                ldm4(a[mt][0], a[mt][1], a[mt][2], a[mt][3],
                     buf + OFF_AL + aRow + mt * (16 * LDT) + kb);
#pragma unroll
            for (int mt = 0; mt < 4; mt++)
#pragma unroll
                for (int nt = 0; nt < 4; nt++)
                    mma16816(acc[mt][nt], a[mt], bh[nt]);
        }
        __syncthreads();
    }

    // ---- epilogue: fragment -> gmem (8-pixel runs are 32B-contiguous) ----
    const int grp = lane >> 2;
#pragma unroll
    for (int mt = 0; mt < 4; mt++) {
#pragma unroll
        for (int half = 0; half < 2; half++) {
            int p = c0 + wm * 64 + mt * 16 + grp + half * 8;
            int hp = p / 66, wp = p - hp * 66;
            if (hp < 1 || hp > 64 || wp < 1 || wp > 64) continue;
            size_t base = (((size_t)b * COUT + co0 + wn * 32) * H_ + (hp - 1)) * W_
                          + (wp - 1);
#pragma unroll
            for (int nt = 0; nt < 4; nt++) {
                int cofs = nt * 8 + (lane & 3) * 2;
                out[base + (size_t)cofs * (H_ * W_)]       = acc[mt][nt][half * 2];
                out[base + (size_t)(cofs + 1) * (H_ * W_)] = acc[mt][nt][half * 2 + 1];
            }
        }
    }
}

// ---------------------------------------------------------------------------
extern "C" void kernel_launch(void* const* d_in, const int* in_sizes, int n_in,
                              void* d_out, int out_size) {
    const float* x       = (const float*)d_in[0];
    const float* thetas  = (const float*)d_in[1];
    const float* scales  = (const float*)d_in[2];
    const float* lambdas = (const float*)d_in[3];
    const float* weight  = (const float*)d_in[4];
    float* out = (float*)d_out;

    cudaFuncSetAttribute(conv_mma_kernel,
                         cudaFuncAttributeMaxDynamicSharedMemorySize, SMEM_BYTES);

    rot_kernel<<<1, 64>>>(thetas, scales, lambdas);
    wtrans_kernel<<<dim3(COUT, B_), 256>>>(weight);
    xzero_kernel<<<2048, 256>>>();
    xprep_kernel<<<dim3(H_, B_), 256>>>(x);
    conv_mma_kernel<<<dim3(NTILES, 2, B_), 256, SMEM_BYTES>>>(out);
}

// round 7
// speedup vs baseline: 4.6732x; 1.0931x over previous
#include <cuda_runtime.h>
#include <cuda_bf16.h>
#include <cstdint>

// Problem dims (fixed by the dataset)
#define B_   16
#define CIN  256
#define COUT 256
#define H_   64
#define W_   64
#define NK   4    // kernel_number n

// Padded-pixel geometry: 66x66 grid flattened; tap shift = (dh-1)*66+(dw-1)
#define POFF   68          // row margin so shifted reads never go negative
#define PROWS  4616
#define NTILE  128         // pixels (M) per CTA
#define NTILES 35          // ceil(4356/128)

typedef unsigned long long u64;

// -------------------- device scratch (static, no allocs) --------------------
__device__ float g_R[B_ * NK * 81];
__device__ __align__(256) __nv_bfloat16 g_xhi[(size_t)B_ * PROWS * CIN];
__device__ __align__(256) __nv_bfloat16 g_xlo[(size_t)B_ * PROWS * CIN];
__device__ __align__(256) __nv_bfloat16 g_whi[(size_t)B_ * 9 * COUT * CIN];
__device__ __align__(256) __nv_bfloat16 g_wlo[(size_t)B_ * 9 * COUT * CIN];

// -------------------- PTX helpers (plain sm_90-safe, no 'a' features) ------
__device__ __forceinline__ uint32_t smem_u32(const void* p) {
    uint32_t a;
    asm("{ .reg .u64 t; cvta.to.shared.u64 t, %1; cvt.u32.u64 %0, t; }"
        : "=r"(a) : "l"(p));
    return a;
}

#define CP16(dst, src) \
    asm volatile("cp.async.cg.shared.global [%0], [%1], 16;" \
                 :: "r"(dst), "l"(src) : "memory")
#define CP_COMMIT() asm volatile("cp.async.commit_group;" ::: "memory")
#define CP_WAIT1()  asm volatile("cp.async.wait_group 1;" ::: "memory")
#define CP_WAIT0()  asm volatile("cp.async.wait_group 0;" ::: "memory")

__device__ __forceinline__ void ldm4(uint32_t& r0, uint32_t& r1,
                                     uint32_t& r2, uint32_t& r3, uint32_t a) {
    asm volatile("ldmatrix.sync.aligned.m8n8.x4.shared.b16 {%0,%1,%2,%3}, [%4];"
                 : "=r"(r0), "=r"(r1), "=r"(r2), "=r"(r3) : "r"(a));
}

__device__ __forceinline__ void mma16816(float* c, const uint32_t* a,
                                         const uint32_t* b) {
    asm volatile(
        "mma.sync.aligned.m16n8k16.row.col.f32.bf16.bf16.f32 "
        "{%0,%1,%2,%3}, {%4,%5,%6,%7}, {%8,%9}, {%0,%1,%2,%3};"
        : "+f"(c[0]), "+f"(c[1]), "+f"(c[2]), "+f"(c[3])
        : "r"(a[0]), "r"(a[1]), "r"(a[2]), "r"(a[3]), "r"(b[0]), "r"(b[1]));
}

// ---------------------------------------------------------------------------
// Kernel A: rot matrices (one thread per (b,n)), scaled by lambda.
// ---------------------------------------------------------------------------
__global__ void rot_kernel(const float* __restrict__ thetas,
                           const float* __restrict__ scales,
                           const float* __restrict__ lambdas) {
    int id = threadIdx.x;
    if (id >= B_ * NK) return;
    float t = thetas[id];
    float s = scales[id];
    float lam = lambdas[id];

    float x = cosf(t) * s;
    float y = sinf(t) * s;

    float m[81];
#pragma unroll
    for (int k = 0; k < 81; k++) m[k] = 0.f;
    m[4 * 9 + 4] = 1.f;

#define SET(r, c, v) m[(r) * 9 + (c)] = (v)
    bool pos = (t >= 0.f);
    bool big = (s >= 1.f);
    bool one = (fabsf(t) <= 0.78539816339744830962f);

    if (pos) {
        float a = x - y, b = x * y, c = x + y;
        float d = a * c, e = a + c;
        if (one && big) {
            SET(0,0,a);     SET(0,1,1.f-a);
            SET(1,1,1.f-y); SET(1,2,y);
            SET(2,2,a);     SET(2,5,1.f-a);
            SET(3,0,y);     SET(3,3,1.f-y);
            SET(5,5,1.f-y); SET(5,8,y);
            SET(6,3,1.f-a); SET(6,6,a);
            SET(7,6,y);     SET(7,7,1.f-y);
            SET(8,7,1.f-a); SET(8,8,a);
        } else if (one) {
            SET(0,0,d);       SET(0,1,a-d);     SET(0,3,c-d);     SET(0,4,1.f-e+d);
            SET(1,1,x-b);     SET(1,2,b);       SET(1,4,1.f-c+b); SET(1,5,y-b);
            SET(2,1,c-d);     SET(2,2,d);       SET(2,4,1.f-e+d); SET(2,5,a-d);
            SET(3,0,b);       SET(3,1,y-b);     SET(3,3,x-b);     SET(3,4,1.f-c+b);
            SET(5,4,1.f-c+b); SET(5,5,x-b);     SET(5,7,y-b);     SET(5,8,b);
            SET(6,3,a-d);     SET(6,4,1.f-e+d); SET(6,6,d);       SET(6,7,c-d);
            SET(7,3,y-b);     SET(7,4,1.f-c+b); SET(7,6,b);       SET(7,7,x-b);
            SET(8,4,1.f-e+d); SET(8,5,c-d);     SET(8,7,a-d);     SET(8,8,d);
        } else {
            SET(0,0,a);       SET(0,1,1.f-a);
            SET(1,1,x-b);     SET(1,2,b);       SET(1,4,1.f-c+b); SET(1,5,y-b);
            SET(2,2,a);       SET(2,5,1.f-a);
            SET(3,0,b);       SET(3,1,y-b);     SET(3,3,x-b);     SET(3,4,1.f-c+b);
            SET(5,4,1.f-c+b); SET(5,5,x-b);     SET(5,7,y-b);     SET(5,8,b);
            SET(6,3,1.f-a);   SET(6,6,a);
            SET(7,3,y-b);     SET(7,4,1.f-c+b); SET(7,6,b);       SET(7,7,x-b);
            SET(8,7,1.f-a);   SET(8,8,a);
        }
    } else {
        float yp = -y;
        float ap = x - yp, bp = x * yp, cp = x + yp;
        float dp = ap * cp, ep = ap + cp;
        if (one && big) {
            SET(0,0,cp);     SET(0,3,1.f-cp);
            SET(1,0,yp);     SET(1,1,1.f-yp);
            SET(2,1,1.f-cp); SET(2,2,cp);
            SET(3,3,1.f-yp); SET(3,6,yp);
            SET(5,2,yp);     SET(5,5,1.f-yp);
            SET(6,6,cp);     SET(6,7,1.f-cp);
            SET(7,7,1.f-yp); SET(7,8,yp);
            SET(8,5,1.f-cp); SET(8,8,cp);
        } else if (one) {
            SET(0,0,dp);        SET(0,1,cp-dp);     SET(0,3,ap-dp);     SET(0,4,1.f-ep+dp);
            SET(1,0,bp);        SET(1,1,x-bp);      SET(1,3,yp-bp);     SET(1,4,1.f-cp+bp);
            SET(2,1,ap-dp);     SET(2,2,dp);        SET(2,4,1.f-ep+dp); SET(2,5,cp-dp);
            SET(3,1,yp-bp);     SET(3,2,bp);        SET(3,4,1.f-cp+bp); SET(3,5,x-bp);
            SET(5,3,x-bp);      SET(5,4,1.f-cp+bp); SET(5,6,bp);        SET(5,7,yp-bp);
            SET(6,3,cp-dp);     SET(6,4,1.f-ep+dp); SET(6,6,dp);        SET(6,7,ap-dp);
            SET(7,4,1.f-cp+bp); SET(7,5,yp-bp);     SET(7,7,x-bp);      SET(7,8,bp);
            SET(8,4,1.f-ep+dp); SET(8,5,ap-dp);     SET(8,7,cp-dp);     SET(8,8,dp);
        } else {
            SET(0,0,cp);        SET(0,3,1.f-cp);
            SET(1,0,bp);        SET(1,1,x-bp);      SET(1,3,yp-bp);     SET(1,4,1.f-cp+bp);
            SET(2,1,1.f-cp);    SET(2,2,cp);
            SET(3,3,x-bp);      SET(3,4,1.f-cp+bp); SET(3,6,bp);        SET(3,7,yp-bp);
            SET(5,1,yp-bp);     SET(5,2,bp);        SET(5,4,1.f-cp+bp); SET(5,5,x-bp);
            SET(6,6,cp);        SET(6,7,1.f-cp);
            SET(7,4,1.f-cp+bp); SET(7,5,yp-bp);     SET(7,7,x-bp);      SET(7,8,bp);
            SET(8,5,1.f-cp);    SET(8,8,cp);
        }
    }
#undef SET

    float* dst = g_R + id * 81;
#pragma unroll
    for (int k = 0; k < 81; k++) dst[k] = lam * m[k];
}

// ---------------------------------------------------------------------------
// Kernel B: weight transform + bf16 hi/lo split.
// ---------------------------------------------------------------------------
__global__ void wtrans_kernel(const float* __restrict__ weight) {
    int o = blockIdx.x;     // co
    int b = blockIdx.y;
    int c = threadIdx.x;    // ci

    __shared__ float Rs[NK * 81];
    for (int k = threadIdx.x; k < NK * 81; k += blockDim.x)
        Rs[k] = g_R[b * NK * 81 + k];
    __syncthreads();

    float acc[9];
#pragma unroll
    for (int i = 0; i < 9; i++) acc[i] = 0.f;

#pragma unroll
    for (int n = 0; n < NK; n++) {
        float w9[9];
        const float* wp = weight + (((size_t)n * COUT + o) * CIN + c) * 9;
#pragma unroll
        for (int j = 0; j < 9; j++) w9[j] = wp[j];
#pragma unroll
        for (int i = 0; i < 9; i++)
#pragma unroll
            for (int j = 0; j < 9; j++)
                acc[i] += Rs[n * 81 + i * 9 + j] * w9[j];
    }

#pragma unroll
    for (int i = 0; i < 9; i++) {
        __nv_bfloat16 hi = __float2bfloat16(acc[i]);
        __nv_bfloat16 lo = __float2bfloat16(acc[i] - __bfloat162float(hi));
        size_t idx = (((size_t)b * 9 + i) * COUT + o) * CIN + c;
        g_whi[idx] = hi;
        g_wlo[idx] = lo;
    }
}

// ---------------------------------------------------------------------------
// Kernel Z: zero the padded transposed-x buffers (margins + zero padding).
// ---------------------------------------------------------------------------
__global__ void xzero_kernel() {
    size_t n16 = ((size_t)B_ * PROWS * CIN * 2) / 16;
    uint4 z = make_uint4(0, 0, 0, 0);
    uint4* a = (uint4*)g_xhi;
    uint4* b = (uint4*)g_xlo;
    for (size_t i = blockIdx.x * blockDim.x + threadIdx.x; i < n16;
         i += (size_t)gridDim.x * blockDim.x) {
        a[i] = z;
        b[i] = z;
    }
}

// ---------------------------------------------------------------------------
// Kernel X: transpose + pad + bf16 split of x into g_x{hi,lo}[b][pixel][ci].
// ---------------------------------------------------------------------------
__global__ void xprep_kernel(const float* __restrict__ x) {
    __shared__ float t[64][65];
    int h = blockIdx.x, b = blockIdx.y;

    for (int ci0 = 0; ci0 < CIN; ci0 += 64) {
        __syncthreads();
        for (int i = threadIdx.x; i < 64 * 64; i += 256) {
            int cl = i >> 6, w = i & 63;
            t[cl][w] = x[(((size_t)b * CIN + ci0 + cl) * H_ + h) * W_ + w];
        }
        __syncthreads();
        for (int i = threadIdx.x; i < 64 * 64; i += 256) {
            int w = i >> 6, cl = i & 63;
            float v = t[cl][w];
            __nv_bfloat16 hi = __float2bfloat16(v);
            __nv_bfloat16 lo = __float2bfloat16(v - __bfloat162float(hi));
            size_t row = (size_t)b * PROWS + ((h + 1) * 66 + (w + 1) + POFF);
            g_xhi[row * CIN + ci0 + cl] = hi;
            g_xlo[row * CIN + ci0 + cl] = lo;
        }
    }
}

// ---------------------------------------------------------------------------
// Kernel C: implicit-GEMM conv via mma.sync (bf16, fp32 accum).
// CTA: 128 pixels x 256 cout (full N), 8 warps (2M x 4N), warp tile 64x64.
// 36 stages (9 taps x 4 ci-chunks of 64), cp.async double-buffered.
// ---------------------------------------------------------------------------
#define LDT     144u                 // smem row stride bytes (9 x 16B)
#define A_TILE  (128u * LDT)         // 18432 B
#define B_TILE  (256u * LDT)         // 36864 B
#define OFF_AH  0u
#define OFF_AL  A_TILE
#define OFF_BH  (2u * A_TILE)
#define OFF_BL  (2u * A_TILE + B_TILE)
#define STG_B   (2u * A_TILE + 2u * B_TILE)   // 110592 B per stage
#define SMEM_BYTES (2u * STG_B)               // 221184 B

__device__ __forceinline__ void stage_tiles(uint32_t sdst,
                                            const char* Xh, const char* Xl,
                                            const char* Wh, const char* Wl,
                                            int c0, int st, int tid) {
    const int tap = st >> 2, kc = st & 3;
    const int dlt = (tap / 3 - 1) * 66 + (tap % 3) - 1;
    const char* sAh = Xh + ((size_t)(c0 + dlt + POFF) * CIN + kc * 64) * 2;
    const char* sAl = Xl + ((size_t)(c0 + dlt + POFF) * CIN + kc * 64) * 2;
    const char* sBh = Wh + ((size_t)tap * COUT * CIN + kc * 64) * 2;
    const char* sBl = Wl + ((size_t)tap * COUT * CIN + kc * 64) * 2;
    // A: 128 rows x 8 segs (hi + lo)
#pragma unroll
    for (int j = 0; j < 4; j++) {
        int idx = j * 256 + tid;              // 0..1023
        int row = idx >> 3, seg = idx & 7;
        uint32_t d = sdst + row * LDT + seg * 16;
        size_t  so = (size_t)row * (CIN * 2) + seg * 16;
        CP16(d + OFF_AH, sAh + so);
        CP16(d + OFF_AL, sAl + so);
    }
    // B: 256 rows x 8 segs (hi + lo)
#pragma unroll
    for (int j = 0; j < 8; j++) {
        int idx = j * 256 + tid;              // 0..2047
        int row = idx >> 3, seg = idx & 7;
        uint32_t d = sdst + row * LDT + seg * 16;
        size_t  so = (size_t)row * (CIN * 2) + seg * 16;
        CP16(d + OFF_BH, sBh + so);
        CP16(d + OFF_BL, sBl + so);
    }
}

__global__ void __launch_bounds__(256, 1)
conv_mma_kernel(float* __restrict__ out) {
    extern __shared__ char smem[];
    const uint32_t sb = smem_u32(smem);

    const int tid = threadIdx.x;
    const int wid = tid >> 5, lane = tid & 31;
    const int wm = wid >> 2;         // 0..1 : M half (64 rows)
    const int wn = wid & 3;          // 0..3 : N quarter (64 cols)
    const int tile = blockIdx.x, b = blockIdx.y;
    const int c0 = tile * NTILE;

    const char* Xh = (const char*)(g_xhi + (size_t)b * PROWS * CIN);
    const char* Xl = (const char*)(g_xlo + (size_t)b * PROWS * CIN);
    const char* Wh = (const char*)(g_whi + (size_t)b * 9 * COUT * CIN);
    const char* Wl = (const char*)(g_wlo + (size_t)b * 9 * COUT * CIN);

    float acc[4][8][4];
#pragma unroll
    for (int mt = 0; mt < 4; mt++)
#pragma unroll
        for (int nt = 0; nt < 8; nt++)
#pragma unroll
            for (int k = 0; k < 4; k++) acc[mt][nt][k] = 0.f;

    // per-lane ldmatrix address components
    const uint32_t aRow = (uint32_t)(wm * 64 + (lane & 15)) * LDT + (lane >> 4) * 16;
    const uint32_t bRow = (uint32_t)(wn * 64 + ((lane >> 4) * 8 + (lane & 7))) * LDT
                          + ((lane >> 3) & 1) * 16;

    stage_tiles(sb, Xh, Xl, Wh, Wl, c0, 0, tid);
    CP_COMMIT();

    for (int st = 0; st < 36; st++) {
        if (st + 1 < 36) {
            stage_tiles(sb + ((st + 1) & 1) * STG_B, Xh, Xl, Wh, Wl,
                        c0, st + 1, tid);
            CP_COMMIT();
            CP_WAIT1();
        } else {
            CP_WAIT0();
        }
        __syncthreads();

        const uint32_t buf = sb + (st & 1) * STG_B;
#pragma unroll
        for (int ks = 0; ks < 4; ks++) {
            const uint32_t kb = ks * 32;
            uint32_t ah[4][4], al[4][4];
#pragma unroll
            for (int mt = 0; mt < 4; mt++)
                ldm4(ah[mt][0], ah[mt][1], ah[mt][2], ah[mt][3],
                     buf + OFF_AH + aRow + mt * (16 * LDT) + kb);
#pragma unroll
            for (int mt = 0; mt < 4; mt++)
                ldm4(al[mt][0], al[mt][1], al[mt][2], al[mt][3],
                     buf + OFF_AL + aRow + mt * (16 * LDT) + kb);
#pragma unroll
            for (int pr = 0; pr < 4; pr++) {     // nt pairs
                uint32_t bh[2][2], bl[2][2];
                ldm4(bh[0][0], bh[0][1], bh[1][0], bh[1][1],
                     buf + OFF_BH + bRow + pr * (16 * LDT) + kb);
                ldm4(bl[0][0], bl[0][1], bl[1][0], bl[1][1],
                     buf + OFF_BL + bRow + pr * (16 * LDT) + kb);
#pragma unroll
                for (int mt = 0; mt < 4; mt++) {
                    mma16816(acc[mt][pr * 2],     ah[mt], bh[0]);
                    mma16816(acc[mt][pr * 2 + 1], ah[mt], bh[1]);
                    mma16816(acc[mt][pr * 2],     ah[mt], bl[0]);
                    mma16816(acc[mt][pr * 2 + 1], ah[mt], bl[1]);
                    mma16816(acc[mt][pr * 2],     al[mt], bh[0]);
                    mma16816(acc[mt][pr * 2 + 1], al[mt], bh[1]);
                }
            }
        }
        __syncthreads();
    }

    // ---- epilogue: fragment -> gmem ----
    const int grp = lane >> 2;
#pragma unroll
    for (int mt = 0; mt < 4; mt++) {
#pragma unroll
        for (int half = 0; half < 2; half++) {
            int p = c0 + wm * 64 + mt * 16 + grp + half * 8;
            int hp = p / 66, wp = p - hp * 66;
            if (hp < 1 || hp > 64 || wp < 1 || wp > 64) continue;
            size_t base = (((size_t)b * COUT + wn * 64) * H_ + (hp - 1)) * W_
                          + (wp - 1);
#pragma unroll
            for (int nt = 0; nt < 8; nt++) {
                int cofs = nt * 8 + (lane & 3) * 2;
                out[base + (size_t)cofs * (H_ * W_)]       = acc[mt][nt][half * 2];
                out[base + (size_t)(cofs + 1) * (H_ * W_)] = acc[mt][nt][half * 2 + 1];
            }
        }
    }
}

// ---------------------------------------------------------------------------
extern "C" void kernel_launch(void* const* d_in, const int* in_sizes, int n_in,
                              void* d_out, int out_size) {
    const float* x       = (const float*)d_in[0];
    const float* thetas  = (const float*)d_in[1];
    const float* scales  = (const float*)d_in[2];
    const float* lambdas = (const float*)d_in[3];
    const float* weight  = (const float*)d_in[4];
    float* out = (float*)d_out;

    cudaFuncSetAttribute(conv_mma_kernel,
                         cudaFuncAttributeMaxDynamicSharedMemorySize, SMEM_BYTES);

    rot_kernel<<<1, 64>>>(thetas, scales, lambdas);
    wtrans_kernel<<<dim3(COUT, B_), 256>>>(weight);
    xzero_kernel<<<2048, 256>>>();
    xprep_kernel<<<dim3(H_, B_), 256>>>(x);
    conv_mma_kernel<<<dim3(NTILES, B_), 256, SMEM_BYTES>>>(out);
}

// round 8
// speedup vs baseline: 9.7393x; 2.0841x over previous
#include <cuda_runtime.h>
#include <cuda_fp16.h>
#include <cstdint>

// Problem dims (fixed by the dataset)
#define B_   16
#define CIN  256
#define COUT 256
#define H_   64
#define W_   64
#define NK   4    // kernel_number n

// Padded-pixel geometry: 66x66 grid flattened; tap shift = (dh-1)*66+(dw-1)
#define POFF   68          // row margin so shifted reads never go negative
#define PROWS  4616
#define NTILE  128         // pixels (M) per CTA
#define NTILES 35          // ceil(4356/128)

// -------------------- device scratch (static, no allocs) --------------------
__device__ float g_R[B_ * NK * 81];
__device__ __align__(256) __half g_x16[(size_t)B_ * PROWS * CIN];
__device__ __align__(256) __half g_w16[(size_t)B_ * 9 * COUT * CIN];

// -------------------- PTX helpers (plain sm_90-safe, no 'a' features) ------
__device__ __forceinline__ uint32_t smem_u32(const void* p) {
    uint32_t a;
    asm("{ .reg .u64 t; cvta.to.shared.u64 t, %1; cvt.u32.u64 %0, t; }"
        : "=r"(a) : "l"(p));
    return a;
}

#define CP16(dst, src) \
    asm volatile("cp.async.cg.shared.global [%0], [%1], 16;" \
                 :: "r"(dst), "l"(src) : "memory")
#define CP_COMMIT() asm volatile("cp.async.commit_group;" ::: "memory")
#define CP_WAIT1()  asm volatile("cp.async.wait_group 1;" ::: "memory")
#define CP_WAIT0()  asm volatile("cp.async.wait_group 0;" ::: "memory")

__device__ __forceinline__ void ldm4(uint32_t& r0, uint32_t& r1,
                                     uint32_t& r2, uint32_t& r3, uint32_t a) {
    asm volatile("ldmatrix.sync.aligned.m8n8.x4.shared.b16 {%0,%1,%2,%3}, [%4];"
                 : "=r"(r0), "=r"(r1), "=r"(r2), "=r"(r3) : "r"(a));
}

__device__ __forceinline__ void mma16816(float* c, const uint32_t* a,
                                         const uint32_t* b) {
    asm volatile(
        "mma.sync.aligned.m16n8k16.row.col.f32.f16.f16.f32 "
        "{%0,%1,%2,%3}, {%4,%5,%6,%7}, {%8,%9}, {%0,%1,%2,%3};"
        : "+f"(c[0]), "+f"(c[1]), "+f"(c[2]), "+f"(c[3])
        : "r"(a[0]), "r"(a[1]), "r"(a[2]), "r"(a[3]), "r"(b[0]), "r"(b[1]));
}

// ---------------------------------------------------------------------------
// Kernel A: rot matrices (one thread per (b,n)), scaled by lambda.
// ---------------------------------------------------------------------------
__global__ void rot_kernel(const float* __restrict__ thetas,
                           const float* __restrict__ scales,
                           const float* __restrict__ lambdas) {
    int id = threadIdx.x;
    if (id >= B_ * NK) return;
    float t = thetas[id];
    float s = scales[id];
    float lam = lambdas[id];

    float x = cosf(t) * s;
    float y = sinf(t) * s;

    float m[81];
#pragma unroll
    for (int k = 0; k < 81; k++) m[k] = 0.f;
    m[4 * 9 + 4] = 1.f;

#define SET(r, c, v) m[(r) * 9 + (c)] = (v)
    bool pos = (t >= 0.f);
    bool big = (s >= 1.f);
    bool one = (fabsf(t) <= 0.78539816339744830962f);

    if (pos) {
        float a = x - y, b = x * y, c = x + y;
        float d = a * c, e = a + c;
        if (one && big) {
            SET(0,0,a);     SET(0,1,1.f-a);
            SET(1,1,1.f-y); SET(1,2,y);
            SET(2,2,a);     SET(2,5,1.f-a);
            SET(3,0,y);     SET(3,3,1.f-y);
            SET(5,5,1.f-y); SET(5,8,y);
            SET(6,3,1.f-a); SET(6,6,a);
            SET(7,6,y);     SET(7,7,1.f-y);
            SET(8,7,1.f-a); SET(8,8,a);
        } else if (one) {
            SET(0,0,d);       SET(0,1,a-d);     SET(0,3,c-d);     SET(0,4,1.f-e+d);
            SET(1,1,x-b);     SET(1,2,b);       SET(1,4,1.f-c+b); SET(1,5,y-b);
            SET(2,1,c-d);     SET(2,2,d);       SET(2,4,1.f-e+d); SET(2,5,a-d);
            SET(3,0,b);       SET(3,1,y-b);     SET(3,3,x-b);     SET(3,4,1.f-c+b);
            SET(5,4,1.f-c+b); SET(5,5,x-b);     SET(5,7,y-b);     SET(5,8,b);
            SET(6,3,a-d);     SET(6,4,1.f-e+d); SET(6,6,d);       SET(6,7,c-d);
            SET(7,3,y-b);     SET(7,4,1.f-c+b); SET(7,6,b);       SET(7,7,x-b);
            SET(8,4,1.f-e+d); SET(8,5,c-d);     SET(8,7,a-d);     SET(8,8,d);
        } else {
            SET(0,0,a);       SET(0,1,1.f-a);
            SET(1,1,x-b);     SET(1,2,b);       SET(1,4,1.f-c+b); SET(1,5,y-b);
            SET(2,2,a);       SET(2,5,1.f-a);
            SET(3,0,b);       SET(3,1,y-b);     SET(3,3,x-b);     SET(3,4,1.f-c+b);
            SET(5,4,1.f-c+b); SET(5,5,x-b);     SET(5,7,y-b);     SET(5,8,b);
            SET(6,3,1.f-a);   SET(6,6,a);
            SET(7,3,y-b);     SET(7,4,1.f-c+b); SET(7,6,b);       SET(7,7,x-b);
            SET(8,7,1.f-a);   SET(8,8,a);
        }
    } else {
        float yp = -y;
        float ap = x - yp, bp = x * yp, cp = x + yp;
        float dp = ap * cp, ep = ap + cp;
        if (one && big) {
            SET(0,0,cp);     SET(0,3,1.f-cp);
            SET(1,0,yp);     SET(1,1,1.f-yp);
            SET(2,1,1.f-cp); SET(2,2,cp);
            SET(3,3,1.f-yp); SET(3,6,yp);
            SET(5,2,yp);     SET(5,5,1.f-yp);
            SET(6,6,cp);     SET(6,7,1.f-cp);
            SET(7,7,1.f-yp); SET(7,8,yp);
            SET(8,5,1.f-cp); SET(8,8,cp);
        } else if (one) {
            SET(0,0,dp);        SET(0,1,cp-dp);     SET(0,3,ap-dp);     SET(0,4,1.f-ep+dp);
            SET(1,0,bp);        SET(1,1,x-bp);      SET(1,3,yp-bp);     SET(1,4,1.f-cp+bp);
            SET(2,1,ap-dp);     SET(2,2,dp);        SET(2,4,1.f-ep+dp); SET(2,5,cp-dp);
            SET(3,1,yp-bp);     SET(3,2,bp);        SET(3,4,1.f-cp+bp); SET(3,5,x-bp);
            SET(5,3,x-bp);      SET(5,4,1.f-cp+bp); SET(5,6,bp);        SET(5,7,yp-bp);
            SET(6,3,cp-dp);     SET(6,4,1.f-ep+dp); SET(6,6,dp);        SET(6,7,ap-dp);
            SET(7,4,1.f-cp+bp); SET(7,5,yp-bp);     SET(7,7,x-bp);      SET(7,8,bp);
            SET(8,4,1.f-ep+dp); SET(8,5,ap-dp);     SET(8,7,cp-dp);     SET(8,8,dp);
        } else {
            SET(0,0,cp);        SET(0,3,1.f-cp);
            SET(1,0,bp);        SET(1,1,x-bp);      SET(1,3,yp-bp);     SET(1,4,1.f-cp+bp);
            SET(2,1,1.f-cp);    SET(2,2,cp);
            SET(3,3,x-bp);      SET(3,4,1.f-cp+bp); SET(3,6,bp);        SET(3,7,yp-bp);
            SET(5,1,yp-bp);     SET(5,2,bp);        SET(5,4,1.f-cp+bp); SET(5,5,x-bp);
            SET(6,6,cp);        SET(6,7,1.f-cp);
            SET(7,4,1.f-cp+bp); SET(7,5,yp-bp);     SET(7,7,x-bp);      SET(7,8,bp);
            SET(8,5,1.f-cp);    SET(8,8,cp);
        }
    }
#undef SET

    float* dst = g_R + id * 81;
#pragma unroll
    for (int k = 0; k < 81; k++) dst[k] = lam * m[k];
}

// ---------------------------------------------------------------------------
// Kernel B: weight transform -> fp16.
// g_w16[b][tap][co][ci] = fp16( sum_{n,j} R[b][n][tap][j] * W[n][co][ci][j] )
// ---------------------------------------------------------------------------
__global__ void wtrans_kernel(const float* __restrict__ weight) {
    int o = blockIdx.x;     // co
    int b = blockIdx.y;
    int c = threadIdx.x;    // ci

    __shared__ float Rs[NK * 81];
    for (int k = threadIdx.x; k < NK * 81; k += blockDim.x)
        Rs[k] = g_R[b * NK * 81 + k];
    __syncthreads();

    float acc[9];
#pragma unroll
    for (int i = 0; i < 9; i++) acc[i] = 0.f;

#pragma unroll
    for (int n = 0; n < NK; n++) {
        float w9[9];
        const float* wp = weight + (((size_t)n * COUT + o) * CIN + c) * 9;
#pragma unroll
        for (int j = 0; j < 9; j++) w9[j] = wp[j];
#pragma unroll
        for (int i = 0; i < 9; i++)
#pragma unroll
            for (int j = 0; j < 9; j++)
                acc[i] += Rs[n * 81 + i * 9 + j] * w9[j];
    }

#pragma unroll
    for (int i = 0; i < 9; i++) {
        size_t idx = (((size_t)b * 9 + i) * COUT + o) * CIN + c;
        g_w16[idx] = __float2half(acc[i]);
    }
}

// ---------------------------------------------------------------------------
// Kernel Z: zero the padded transposed-x buffer (margins + zero padding).
// ---------------------------------------------------------------------------
__global__ void xzero_kernel() {
    size_t n16 = ((size_t)B_ * PROWS * CIN * 2) / 16;
    uint4 z = make_uint4(0, 0, 0, 0);
    uint4* a = (uint4*)g_x16;
    for (size_t i = blockIdx.x * blockDim.x + threadIdx.x; i < n16;
         i += (size_t)gridDim.x * blockDim.x)
        a[i] = z;
}

// ---------------------------------------------------------------------------
// Kernel X: transpose + pad + fp16 convert of x into g_x16[b][pixel][ci].
// ---------------------------------------------------------------------------
__global__ void xprep_kernel(const float* __restrict__ x) {
    __shared__ float t[64][65];
    int h = blockIdx.x, b = blockIdx.y;

    for (int ci0 = 0; ci0 < CIN; ci0 += 64) {
        __syncthreads();
        for (int i = threadIdx.x; i < 64 * 64; i += 256) {
            int cl = i >> 6, w = i & 63;
            t[cl][w] = x[(((size_t)b * CIN + ci0 + cl) * H_ + h) * W_ + w];
        }
        __syncthreads();
        for (int i = threadIdx.x; i < 64 * 64; i += 256) {
            int w = i >> 6, cl = i & 63;
            size_t row = (size_t)b * PROWS + ((h + 1) * 66 + (w + 1) + POFF);
            g_x16[row * CIN + ci0 + cl] = __float2half(t[cl][w]);
        }
    }
}

// ---------------------------------------------------------------------------
// Kernel C: implicit-GEMM conv via mma.sync (fp16 in, fp32 accum).
// CTA: 128 pixels x 256 cout, 8 warps (2M x 4N), warp tile 64x64.
// 36 stages (9 taps x 4 ci-chunks of 64), cp.async double-buffered.
// ---------------------------------------------------------------------------
#define LDT     144u                 // smem row stride bytes (9 x 16B)
#define A_TILE  (128u * LDT)         // 18432 B
#define B_TILE  (256u * LDT)         // 36864 B
#define OFF_A   0u
#define OFF_B   A_TILE
#define STG_B   (A_TILE + B_TILE)    // 55296 B per stage
#define SMEM_BYTES (2u * STG_B)      // 110592 B

__device__ __forceinline__ void stage_tiles(uint32_t sdst,
                                            const char* X, const char* W,
                                            int c0, int st, int tid) {
    const int tap = st >> 2, kc = st & 3;
    const int dlt = (tap / 3 - 1) * 66 + (tap % 3) - 1;
    const char* sA = X + ((size_t)(c0 + dlt + POFF) * CIN + kc * 64) * 2;
    const char* sB = W + ((size_t)tap * COUT * CIN + kc * 64) * 2;
    // A: 128 rows x 8 segs of 16B
#pragma unroll
    for (int j = 0; j < 4; j++) {
        int idx = j * 256 + tid;              // 0..1023
        int row = idx >> 3, seg = idx & 7;
        CP16(sdst + OFF_A + row * LDT + seg * 16,
             sA + (size_t)row * (CIN * 2) + seg * 16);
    }
    // B: 256 rows x 8 segs of 16B
#pragma unroll
    for (int j = 0; j < 8; j++) {
        int idx = j * 256 + tid;              // 0..2047
        int row = idx >> 3, seg = idx & 7;
        CP16(sdst + OFF_B + row * LDT + seg * 16,
             sB + (size_t)row * (CIN * 2) + seg * 16);
    }
}

__global__ void __launch_bounds__(256, 1)
conv_mma_kernel(float* __restrict__ out) {
    extern __shared__ char smem[];
    const uint32_t sb = smem_u32(smem);

    const int tid = threadIdx.x;
    const int wid = tid >> 5, lane = tid & 31;
    const int wm = wid >> 2;         // 0..1 : M half (64 rows)
    const int wn = wid & 3;          // 0..3 : N quarter (64 cols)
    const int tile = blockIdx.x, b = blockIdx.y;
    const int c0 = tile * NTILE;

    const char* X = (const char*)(g_x16 + (size_t)b * PROWS * CIN);
    const char* W = (const char*)(g_w16 + (size_t)b * 9 * COUT * CIN);

    float acc[4][8][4];
#pragma unroll
    for (int mt = 0; mt < 4; mt++)
#pragma unroll
        for (int nt = 0; nt < 8; nt++)
#pragma unroll
            for (int k = 0; k < 4; k++) acc[mt][nt][k] = 0.f;

    // per-lane ldmatrix address components
    const uint32_t aRow = (uint32_t)(wm * 64 + (lane & 15)) * LDT + (lane >> 4) * 16;
    const uint32_t bRow = (uint32_t)(wn * 64 + ((lane >> 4) * 8 + (lane & 7))) * LDT
                          + ((lane >> 3) & 1) * 16;

    stage_tiles(sb, X, W, c0, 0, tid);
    CP_COMMIT();

    for (int st = 0; st < 36; st++) {
        if (st + 1 < 36) {
            stage_tiles(sb + ((st + 1) & 1) * STG_B, X, W, c0, st + 1, tid);
            CP_COMMIT();
            CP_WAIT1();
        } else {
            CP_WAIT0();
        }
        __syncthreads();

        const uint32_t buf = sb + (st & 1) * STG_B;
#pragma unroll
        for (int ks = 0; ks < 4; ks++) {
            const uint32_t kb = ks * 32;
            uint32_t a[4][4];
#pragma unroll
            for (int mt = 0; mt < 4; mt++)
                ldm4(a[mt][0], a[mt][1], a[mt][2], a[mt][3],
                     buf + OFF_A + aRow + mt * (16 * LDT) + kb);
#pragma unroll
            for (int pr = 0; pr < 4; pr++) {     // nt pairs
                uint32_t bb[2][2];
                ldm4(bb[0][0], bb[0][1], bb[1][0], bb[1][1],
                     buf + OFF_B + bRow + pr * (16 * LDT) + kb);
#pragma unroll
                for (int mt = 0; mt < 4; mt++) {
                    mma16816(acc[mt][pr * 2],     a[mt], bb[0]);
                    mma16816(acc[mt][pr * 2 + 1], a[mt], bb[1]);
                }
            }
        }
        __syncthreads();
    }

    // ---- epilogue: fragment -> gmem ----
    const int grp = lane >> 2;
#pragma unroll
    for (int mt = 0; mt < 4; mt++) {
#pragma unroll
        for (int half = 0; half < 2; half++) {
            int p = c0 + wm * 64 + mt * 16 + grp + half * 8;
            int hp = p / 66, wp = p - hp * 66;
            if (hp < 1 || hp > 64 || wp < 1 || wp > 64) continue;
            size_t base = (((size_t)b * COUT + wn * 64) * H_ + (hp - 1)) * W_
                          + (wp - 1);
#pragma unroll
            for (int nt = 0; nt < 8; nt++) {
                int cofs = nt * 8 + (lane & 3) * 2;
                out[base + (size_t)cofs * (H_ * W_)]       = acc[mt][nt][half * 2];
                out[base + (size_t)(cofs + 1) * (H_ * W_)] = acc[mt][nt][half * 2 + 1];
            }
        }
    }
}

// ---------------------------------------------------------------------------
extern "C" void kernel_launch(void* const* d_in, const int* in_sizes, int n_in,
                              void* d_out, int out_size) {
    const float* x       = (const float*)d_in[0];
    const float* thetas  = (const float*)d_in[1];
    const float* scales  = (const float*)d_in[2];
    const float* lambdas = (const float*)d_in[3];
    const float* weight  = (const float*)d_in[4];
    float* out = (float*)d_out;

    cudaFuncSetAttribute(conv_mma_kernel,
                         cudaFuncAttributeMaxDynamicSharedMemorySize, SMEM_BYTES);

    rot_kernel<<<1, 64>>>(thetas, scales, lambdas);
    wtrans_kernel<<<dim3(COUT, B_), 256>>>(weight);
    xzero_kernel<<<2048, 256>>>();
    xprep_kernel<<<dim3(H_, B_), 256>>>(x);
    conv_mma_kernel<<<dim3(NTILES, B_), 256, SMEM_BYTES>>>(out);
}

// round 9
// speedup vs baseline: 10.9085x; 1.1201x over previous
#include <cuda_runtime.h>
#include <cuda_fp16.h>
#include <cstdint>

// Problem dims (fixed by the dataset)
#define B_   16
#define CIN  256
#define COUT 256
#define H_   64
#define W_   64
#define NK   4    // kernel_number n

// Padded-pixel geometry: 66x66 grid flattened; tap shift = (dh-1)*66+(dw-1)
#define POFF   68          // row margin so shifted reads never go negative
#define PROWS  4616
#define NTILE  128         // pixels (M) per CTA
#define NTILES 35          // ceil(4356/128)

// -------------------- device scratch (static, no allocs) --------------------
__device__ float g_R[B_ * NK * 81];
__device__ __align__(256) __half g_x16[(size_t)B_ * PROWS * CIN];
__device__ __align__(256) __half g_w16[(size_t)B_ * 9 * COUT * CIN];

// -------------------- PTX helpers (plain sm_90-safe, no 'a' features) ------
__device__ __forceinline__ uint32_t smem_u32(const void* p) {
    uint32_t a;
    asm("{ .reg .u64 t; cvta.to.shared.u64 t, %1; cvt.u32.u64 %0, t; }"
        : "=r"(a) : "l"(p));
    return a;
}

#define CP16(dst, src) \
    asm volatile("cp.async.cg.shared.global [%0], [%1], 16;" \
                 :: "r"(dst), "l"(src) : "memory")
#define CP_COMMIT() asm volatile("cp.async.commit_group;" ::: "memory")
#define CP_WAIT1()  asm volatile("cp.async.wait_group 1;" ::: "memory")
#define CP_WAIT0()  asm volatile("cp.async.wait_group 0;" ::: "memory")

__device__ __forceinline__ void ldm4(uint32_t& r0, uint32_t& r1,
                                     uint32_t& r2, uint32_t& r3, uint32_t a) {
    asm volatile("ldmatrix.sync.aligned.m8n8.x4.shared.b16 {%0,%1,%2,%3}, [%4];"
                 : "=r"(r0), "=r"(r1), "=r"(r2), "=r"(r3) : "r"(a));
}

__device__ __forceinline__ void mma16816(float* c, const uint32_t* a,
                                         const uint32_t* b) {
    asm volatile(
        "mma.sync.aligned.m16n8k16.row.col.f32.f16.f16.f32 "
        "{%0,%1,%2,%3}, {%4,%5,%6,%7}, {%8,%9}, {%0,%1,%2,%3};"
        : "+f"(c[0]), "+f"(c[1]), "+f"(c[2]), "+f"(c[3])
        : "r"(a[0]), "r"(a[1]), "r"(a[2]), "r"(a[3]), "r"(b[0]), "r"(b[1]));
}

// ---------------------------------------------------------------------------
// Kernel A: rot matrices (one thread per (b,n)), scaled by lambda.
// ---------------------------------------------------------------------------
__global__ void rot_kernel(const float* __restrict__ thetas,
                           const float* __restrict__ scales,
                           const float* __restrict__ lambdas) {
    int id = threadIdx.x;
    if (id >= B_ * NK) return;
    float t = thetas[id];
    float s = scales[id];
    float lam = lambdas[id];

    float x = cosf(t) * s;
    float y = sinf(t) * s;

    float m[81];
#pragma unroll
    for (int k = 0; k < 81; k++) m[k] = 0.f;
    m[4 * 9 + 4] = 1.f;

#define SET(r, c, v) m[(r) * 9 + (c)] = (v)
    bool pos = (t >= 0.f);
    bool big = (s >= 1.f);
    bool one = (fabsf(t) <= 0.78539816339744830962f);

    if (pos) {
        float a = x - y, b = x * y, c = x + y;
        float d = a * c, e = a + c;
        if (one && big) {
            SET(0,0,a);     SET(0,1,1.f-a);
            SET(1,1,1.f-y); SET(1,2,y);
            SET(2,2,a);     SET(2,5,1.f-a);
            SET(3,0,y);     SET(3,3,1.f-y);
            SET(5,5,1.f-y); SET(5,8,y);
            SET(6,3,1.f-a); SET(6,6,a);
            SET(7,6,y);     SET(7,7,1.f-y);
            SET(8,7,1.f-a); SET(8,8,a);
        } else if (one) {
            SET(0,0,d);       SET(0,1,a-d);     SET(0,3,c-d);     SET(0,4,1.f-e+d);
            SET(1,1,x-b);     SET(1,2,b);       SET(1,4,1.f-c+b); SET(1,5,y-b);
            SET(2,1,c-d);     SET(2,2,d);       SET(2,4,1.f-e+d); SET(2,5,a-d);
            SET(3,0,b);       SET(3,1,y-b);     SET(3,3,x-b);     SET(3,4,1.f-c+b);
            SET(5,4,1.f-c+b); SET(5,5,x-b);     SET(5,7,y-b);     SET(5,8,b);
            SET(6,3,a-d);     SET(6,4,1.f-e+d); SET(6,6,d);       SET(6,7,c-d);
            SET(7,3,y-b);     SET(7,4,1.f-c+b); SET(7,6,b);       SET(7,7,x-b);
            SET(8,4,1.f-e+d); SET(8,5,c-d);     SET(8,7,a-d);     SET(8,8,d);
        } else {
            SET(0,0,a);       SET(0,1,1.f-a);
            SET(1,1,x-b);     SET(1,2,b);       SET(1,4,1.f-c+b); SET(1,5,y-b);
            SET(2,2,a);       SET(2,5,1.f-a);
            SET(3,0,b);       SET(3,1,y-b);     SET(3,3,x-b);     SET(3,4,1.f-c+b);
            SET(5,4,1.f-c+b); SET(5,5,x-b);     SET(5,7,y-b);     SET(5,8,b);
            SET(6,3,1.f-a);   SET(6,6,a);
            SET(7,3,y-b);     SET(7,4,1.f-c+b); SET(7,6,b);       SET(7,7,x-b);
            SET(8,7,1.f-a);   SET(8,8,a);
        }
    } else {
        float yp = -y;
        float ap = x - yp, bp = x * yp, cp = x + yp;
        float dp = ap * cp, ep = ap + cp;
        if (one && big) {
            SET(0,0,cp);     SET(0,3,1.f-cp);
            SET(1,0,yp);     SET(1,1,1.f-yp);
            SET(2,1,1.f-cp); SET(2,2,cp);
            SET(3,3,1.f-yp); SET(3,6,yp);
            SET(5,2,yp);     SET(5,5,1.f-yp);
            SET(6,6,cp);     SET(6,7,1.f-cp);
            SET(7,7,1.f-yp); SET(7,8,yp);
            SET(8,5,1.f-cp); SET(8,8,cp);
        } else if (one) {
            SET(0,0,dp);        SET(0,1,cp-dp);     SET(0,3,ap-dp);     SET(0,4,1.f-ep+dp);
            SET(1,0,bp);        SET(1,1,x-bp);      SET(1,3,yp-bp);     SET(1,4,1.f-cp+bp);
            SET(2,1,ap-dp);     SET(2,2,dp);        SET(2,4,1.f-ep+dp); SET(2,5,cp-dp);
            SET(3,1,yp-bp);     SET(3,2,bp);        SET(3,4,1.f-cp+bp); SET(3,5,x-bp);
            SET(5,3,x-bp);      SET(5,4,1.f-cp+bp); SET(5,6,bp);        SET(5,7,yp-bp);
            SET(6,3,cp-dp);     SET(6,4,1.f-ep+dp); SET(6,6,dp);        SET(6,7,ap-dp);
            SET(7,4,1.f-cp+bp); SET(7,5,yp-bp);     SET(7,7,x-bp);      SET(7,8,bp);
            SET(8,4,1.f-ep+dp); SET(8,5,ap-dp);     SET(8,7,cp-dp);     SET(8,8,dp);
        } else {
            SET(0,0,cp);        SET(0,3,1.f-cp);
            SET(1,0,bp);        SET(1,1,x-bp);      SET(1,3,yp-bp);     SET(1,4,1.f-cp+bp);
            SET(2,1,1.f-cp);    SET(2,2,cp);
            SET(3,3,x-bp);      SET(3,4,1.f-cp+bp); SET(3,6,bp);        SET(3,7,yp-bp);
            SET(5,1,yp-bp);     SET(5,2,bp);        SET(5,4,1.f-cp+bp); SET(5,5,x-bp);
            SET(6,6,cp);        SET(6,7,1.f-cp);
            SET(7,4,1.f-cp+bp); SET(7,5,yp-bp);     SET(7,7,x-bp);      SET(7,8,bp);
            SET(8,5,1.f-cp);    SET(8,8,cp);
        }
    }
#undef SET

    float* dst = g_R + id * 81;
#pragma unroll
    for (int k = 0; k < 81; k++) dst[k] = lam * m[k];
}

// ---------------------------------------------------------------------------
// Kernel B: weight transform -> fp16.
// ---------------------------------------------------------------------------
__global__ void wtrans_kernel(const float* __restrict__ weight) {
    int o = blockIdx.x;     // co
    int b = blockIdx.y;
    int c = threadIdx.x;    // ci

    __shared__ float Rs[NK * 81];
    for (int k = threadIdx.x; k < NK * 81; k += blockDim.x)
        Rs[k] = g_R[b * NK * 81 + k];
    __syncthreads();

    float acc[9];
#pragma unroll
    for (int i = 0; i < 9; i++) acc[i] = 0.f;

#pragma unroll
    for (int n = 0; n < NK; n++) {
        float w9[9];
        const float* wp = weight + (((size_t)n * COUT + o) * CIN + c) * 9;
#pragma unroll
        for (int j = 0; j < 9; j++) w9[j] = wp[j];
#pragma unroll
        for (int i = 0; i < 9; i++)
#pragma unroll
            for (int j = 0; j < 9; j++)
                acc[i] += Rs[n * 81 + i * 9 + j] * w9[j];
    }

#pragma unroll
    for (int i = 0; i < 9; i++) {
        size_t idx = (((size_t)b * 9 + i) * COUT + o) * CIN + c;
        g_w16[idx] = __float2half(acc[i]);
    }
}

// ---------------------------------------------------------------------------
// Kernel Z: zero ONLY the margin/padding rows of g_x16 (rows never written
// by xprep). blockDim (32,8): one warp per row, 32 uint4 = 512 B.
// ---------------------------------------------------------------------------
__global__ void xmargin_kernel() {
    int row = blockIdx.x * blockDim.y + threadIdx.y;
    if (row >= B_ * PROWS) return;
    int pr = row % PROWS;
    int p = pr - POFF;
    bool interior = false;
    if (p >= 0 && p < 66 * 66) {
        int hp = p / 66, wp = p - hp * 66;
        interior = (hp >= 1 && hp <= 64 && wp >= 1 && wp <= 64);
    }
    if (!interior) {
        uint4* dst = (uint4*)(g_x16 + (size_t)row * CIN);
        dst[threadIdx.x] = make_uint4(0, 0, 0, 0);
    }
}

// ---------------------------------------------------------------------------
// Kernel X: transpose + pad + fp16 convert of x into g_x16[b][pixel][ci].
// ---------------------------------------------------------------------------
__global__ void xprep_kernel(const float* __restrict__ x) {
    __shared__ float t[64][65];
    int h = blockIdx.x, b = blockIdx.y;

    for (int ci0 = 0; ci0 < CIN; ci0 += 64) {
        __syncthreads();
        for (int i = threadIdx.x; i < 64 * 64; i += 256) {
            int cl = i >> 6, w = i & 63;
            t[cl][w] = x[(((size_t)b * CIN + ci0 + cl) * H_ + h) * W_ + w];
        }
        __syncthreads();
        for (int i = threadIdx.x; i < 64 * 64; i += 256) {
            int w = i >> 6, cl = i & 63;
            size_t row = (size_t)b * PROWS + ((h + 1) * 66 + (w + 1) + POFF);
            g_x16[row * CIN + ci0 + cl] = __float2half(t[cl][w]);
        }
    }
}

// ---------------------------------------------------------------------------
// Kernel C: implicit-GEMM conv via mma.sync (fp16 in, fp32 accum).
// CTA: 128 pixels x 256 cout, 8 warps (2M x 4N), warp tile 64x64.
// 36 stages (9 taps x 4 ci-chunks of 64), cp.async 3-stage ring,
// ONE __syncthreads per stage.
// ---------------------------------------------------------------------------
#define LDT     144u                 // smem row stride bytes (9 x 16B)
#define A_TILE  (128u * LDT)         // 18432 B
#define B_TILE  (256u * LDT)         // 36864 B
#define OFF_A   0u
#define OFF_B   A_TILE
#define STG_B   (A_TILE + B_TILE)    // 55296 B per stage
#define SMEM_BYTES (3u * STG_B)      // 165888 B

__device__ __forceinline__ void stage_tiles(uint32_t sdst,
                                            const char* X, const char* W,
                                            int c0, int st, int tid) {
    const int tap = st >> 2, kc = st & 3;
    const int dlt = (tap / 3 - 1) * 66 + (tap % 3) - 1;
    const char* sA = X + ((size_t)(c0 + dlt + POFF) * CIN + kc * 64) * 2;
    const char* sB = W + ((size_t)tap * COUT * CIN + kc * 64) * 2;
    // A: 128 rows x 8 segs of 16B
#pragma unroll
    for (int j = 0; j < 4; j++) {
        int idx = j * 256 + tid;              // 0..1023
        int row = idx >> 3, seg = idx & 7;
        CP16(sdst + OFF_A + row * LDT + seg * 16,
             sA + (size_t)row * (CIN * 2) + seg * 16);
    }
    // B: 256 rows x 8 segs of 16B
#pragma unroll
    for (int j = 0; j < 8; j++) {
        int idx = j * 256 + tid;              // 0..2047
        int row = idx >> 3, seg = idx & 7;
        CP16(sdst + OFF_B + row * LDT + seg * 16,
             sB + (size_t)row * (CIN * 2) + seg * 16);
    }
}

__global__ void __launch_bounds__(256, 1)
conv_mma_kernel(float* __restrict__ out) {
    extern __shared__ char smem[];
    const uint32_t sb = smem_u32(smem);

    const int tid = threadIdx.x;
    const int wid = tid >> 5, lane = tid & 31;
    const int wm = wid >> 2;         // 0..1 : M half (64 rows)
    const int wn = wid & 3;          // 0..3 : N quarter (64 cols)
    const int tile = blockIdx.x, b = blockIdx.y;
    const int c0 = tile * NTILE;

    const char* X = (const char*)(g_x16 + (size_t)b * PROWS * CIN);
    const char* W = (const char*)(g_w16 + (size_t)b * 9 * COUT * CIN);

    float acc[4][8][4];
#pragma unroll
    for (int mt = 0; mt < 4; mt++)
#pragma unroll
        for (int nt = 0; nt < 8; nt++)
#pragma unroll
            for (int k = 0; k < 4; k++) acc[mt][nt][k] = 0.f;

    // per-lane ldmatrix address components
    const uint32_t aRow = (uint32_t)(wm * 64 + (lane & 15)) * LDT + (lane >> 4) * 16;
    const uint32_t bRow = (uint32_t)(wn * 64 + ((lane >> 4) * 8 + (lane & 7))) * LDT
                          + ((lane >> 3) & 1) * 16;

    stage_tiles(sb + 0u * STG_B, X, W, c0, 0, tid);
    CP_COMMIT();
    stage_tiles(sb + 1u * STG_B, X, W, c0, 1, tid);
    CP_COMMIT();

    int bufSel = 0;                   // st % 3 without modulo
    for (int st = 0; st < 36; st++) {
        if (st < 35) CP_WAIT1(); else CP_WAIT0();
        __syncthreads();              // stage st visible to all; ring slot free

        const uint32_t buf = sb + (uint32_t)bufSel * STG_B;
#pragma unroll
        for (int ks = 0; ks < 4; ks++) {
            const uint32_t kb = ks * 32;
            uint32_t a[4][4];
#pragma unroll
            for (int mt = 0; mt < 4; mt++)
                ldm4(a[mt][0], a[mt][1], a[mt][2], a[mt][3],
                     buf + OFF_A + aRow + mt * (16 * LDT) + kb);
#pragma unroll
            for (int pr = 0; pr < 4; pr++) {     // nt pairs
                uint32_t bb[2][2];
                ldm4(bb[0][0], bb[0][1], bb[1][0], bb[1][1],
                     buf + OFF_B + bRow + pr * (16 * LDT) + kb);
#pragma unroll
                for (int mt = 0; mt < 4; mt++) {
                    mma16816(acc[mt][pr * 2],     a[mt], bb[0]);
                    mma16816(acc[mt][pr * 2 + 1], a[mt], bb[1]);
                }
            }
        }

        if (st + 2 < 36) {
            int slot = bufSel + 2; if (slot >= 3) slot -= 3;
            stage_tiles(sb + (uint32_t)slot * STG_B, X, W, c0, st + 2, tid);
            CP_COMMIT();
        }
        if (++bufSel == 3) bufSel = 0;
    }

    // ---- epilogue: fragment -> gmem ----
    const int grp = lane >> 2;
#pragma unroll
    for (int mt = 0; mt < 4; mt++) {
#pragma unroll
        for (int half = 0; half < 2; half++) {
            int p = c0 + wm * 64 + mt * 16 + grp + half * 8;
            int hp = p / 66, wp = p - hp * 66;
            if (hp < 1 || hp > 64 || wp < 1 || wp > 64) continue;
            size_t base = (((size_t)b * COUT + wn * 64) * H_ + (hp - 1)) * W_
                          + (wp - 1);
#pragma unroll
            for (int nt = 0; nt < 8; nt++) {
                int cofs = nt * 8 + (lane & 3) * 2;
                out[base + (size_t)cofs * (H_ * W_)]       = acc[mt][nt][half * 2];
                out[base + (size_t)(cofs + 1) * (H_ * W_)] = acc[mt][nt][half * 2 + 1];
            }
        }
    }
}

// ---------------------------------------------------------------------------
extern "C" void kernel_launch(void* const* d_in, const int* in_sizes, int n_in,
                              void* d_out, int out_size) {
    const float* x       = (const float*)d_in[0];
    const float* thetas  = (const float*)d_in[1];
    const float* scales  = (const float*)d_in[2];
    const float* lambdas = (const float*)d_in[3];
    const float* weight  = (const float*)d_in[4];
    float* out = (float*)d_out;

    cudaFuncSetAttribute(conv_mma_kernel,
                         cudaFuncAttributeMaxDynamicSharedMemorySize, SMEM_BYTES);

    rot_kernel<<<1, 64>>>(thetas, scales, lambdas);
    wtrans_kernel<<<dim3(COUT, B_), 256>>>(weight);
    {
        int rows = B_ * PROWS;
        dim3 blk(32, 8);
        xmargin_kernel<<<(rows + 7) / 8, blk>>>();
    }
    xprep_kernel<<<dim3(H_, B_), 256>>>(x);
    conv_mma_kernel<<<dim3(NTILES, B_), 256, SMEM_BYTES>>>(out);
}